// round 1
// baseline (speedup 1.0000x reference)
#include <cuda_runtime.h>
#include <math.h>

#define TSEQ   4096
#define DEMB   1024
#define NHEADS 16
#define DKH    64
#define HDIM   1024   // NHEADS * DKH

// Scratch buffers (allocation-free rule: __device__ globals)
__device__ float g_q[TSEQ * HDIM];
__device__ float g_k[TSEQ * HDIM];
__device__ float g_v[TSEQ * HDIM];
__device__ float g_attn[TSEQ * HDIM];

// ---------------------------------------------------------------------------
// SGEMM: C[M,N] = A[M,K] @ B[K,N] + bias[N]    (all row-major, dims % 64 == 0)
// Block: 256 threads, tile 64x64, BK=16, each thread a 4x4 microtile.
// ---------------------------------------------------------------------------
__global__ void sgemm_bias_kernel(const float* __restrict__ A,
                                  const float* __restrict__ B,
                                  const float* __restrict__ bias,
                                  float* __restrict__ C,
                                  int M, int N, int K) {
    __shared__ float As[16][64];   // transposed: As[k][m]
    __shared__ float Bs[16][64];   // Bs[k][n]

    const int tid = threadIdx.x;
    const int gm  = blockIdx.y * 64;
    const int gn  = blockIdx.x * 64;
    const int ty  = tid >> 4;      // 0..15
    const int tx  = tid & 15;      // 0..15

    // load indices
    const int arow  = tid >> 2;    // 0..63
    const int aquad = tid & 3;     // 0..3  (4 floats each)
    const int brow  = tid >> 4;    // 0..15
    const int bcol4 = tid & 15;    // 0..15 (float4 each)

    float acc[4][4] = {};

    for (int k0 = 0; k0 < K; k0 += 16) {
        float4 av = *(const float4*)&A[(gm + arow) * K + k0 + aquad * 4];
        float4 bv = *(const float4*)&B[(k0 + brow) * N + gn + bcol4 * 4];
        __syncthreads();
        As[aquad * 4 + 0][arow] = av.x;
        As[aquad * 4 + 1][arow] = av.y;
        As[aquad * 4 + 2][arow] = av.z;
        As[aquad * 4 + 3][arow] = av.w;
        *(float4*)&Bs[brow][bcol4 * 4] = bv;
        __syncthreads();

#pragma unroll
        for (int k = 0; k < 16; k++) {
            float4 a = *(const float4*)&As[k][ty * 4];
            float4 b = *(const float4*)&Bs[k][tx * 4];
            acc[0][0] += a.x * b.x; acc[0][1] += a.x * b.y; acc[0][2] += a.x * b.z; acc[0][3] += a.x * b.w;
            acc[1][0] += a.y * b.x; acc[1][1] += a.y * b.y; acc[1][2] += a.y * b.z; acc[1][3] += a.y * b.w;
            acc[2][0] += a.z * b.x; acc[2][1] += a.z * b.y; acc[2][2] += a.z * b.z; acc[2][3] += a.z * b.w;
            acc[3][0] += a.w * b.x; acc[3][1] += a.w * b.y; acc[3][2] += a.w * b.z; acc[3][3] += a.w * b.w;
        }
    }

#pragma unroll
    for (int i = 0; i < 4; i++) {
        const int row = gm + ty * 4 + i;
#pragma unroll
        for (int j = 0; j < 4; j++) {
            const int col = gn + tx * 4 + j;
            C[row * N + col] = acc[i][j] + bias[col];
        }
    }
}

// ---------------------------------------------------------------------------
// RoPE applied in-place to Q and K.  grid = TSEQ blocks, 512 threads:
// thread = (head h = tid/32, pair index i = tid%32), dk = 64.
// out[d<32]  = x1*cos(f_i) - x2*sin(f_i)
// out[d>=32] = x2*cos(f_i) + x1*sin(f_i)
// ---------------------------------------------------------------------------
__global__ void rotary_kernel(float* __restrict__ q, float* __restrict__ k) {
    const int t   = blockIdx.x;
    const int tid = threadIdx.x;           // 0..511
    const int h   = tid >> 5;
    const int i   = tid & 31;

    // inv_freq = 10000^(-i/32) = exp2(-i * log2(10000)/32)
    const float inv = exp2f(-(float)i * 0.4152410118609203f);
    const float f   = (float)t * inv;
    float s, c;
    sincosf(f, &s, &c);

    const int base = t * HDIM + h * DKH;
    float q1 = q[base + i], q2 = q[base + i + 32];
    q[base + i]      = q1 * c - q2 * s;
    q[base + i + 32] = q2 * c + q1 * s;
    float k1 = k[base + i], k2 = k[base + i + 32];
    k[base + i]      = k1 * c - k2 * s;
    k[base + i + 32] = k2 * c + k1 * s;
}

// ---------------------------------------------------------------------------
// Flash attention (non-causal, full).  One block = (head, 64-query tile).
// 256 threads: thread (r = tid/4, quarter = tid%4). Thread owns
// O[r][quarter*16 .. +16] accumulators; S tile cols [quarter*16 .. +16).
// Streams 64-key tiles with online softmax.
// ---------------------------------------------------------------------------
#define SMEM_STRIDE 68

__global__ void flash_attn_kernel(const float* __restrict__ Q,
                                  const float* __restrict__ K,
                                  const float* __restrict__ V,
                                  float* __restrict__ O) {
    extern __shared__ float sm[];
    float (*Qs)[SMEM_STRIDE] = (float (*)[SMEM_STRIDE])(sm);
    float (*Ks)[SMEM_STRIDE] = (float (*)[SMEM_STRIDE])(sm + 64 * SMEM_STRIDE);
    float (*Vs)[SMEM_STRIDE] = (float (*)[SMEM_STRIDE])(sm + 2 * 64 * SMEM_STRIDE);
    float (*Ps)[SMEM_STRIDE] = (float (*)[SMEM_STRIDE])(sm + 3 * 64 * SMEM_STRIDE);
    __shared__ float redmax[64][4];
    __shared__ float redsum[64][4];

    const int h   = blockIdx.y;
    const int q0  = blockIdx.x * 64;
    const int tid = threadIdx.x;
    const int r   = tid >> 2;      // 0..63 query row within tile
    const int qr  = tid & 3;       // 0..3  quarter
    const int hof = h * DKH;
    const float scale = 0.125f;    // 1/sqrt(64)

    // Load Q tile (each thread: 16 contiguous floats of one row)
    {
        const float* src = &Q[(q0 + r) * HDIM + hof + qr * 16];
        float* dst = &Qs[r][qr * 16];
#pragma unroll
        for (int j = 0; j < 4; j++)
            *(float4*)&dst[j * 4] = *(const float4*)&src[j * 4];
    }

    float m_run = -INFINITY;
    float l_run = 0.0f;
    float oacc[16];
#pragma unroll
    for (int j = 0; j < 16; j++) oacc[j] = 0.0f;

    for (int kv0 = 0; kv0 < TSEQ; kv0 += 64) {
        __syncthreads();   // protect Ks/Vs/Ps from previous iteration readers

        // Load K and V tiles
        {
            const float* ksrc = &K[(kv0 + r) * HDIM + hof + qr * 16];
            const float* vsrc = &V[(kv0 + r) * HDIM + hof + qr * 16];
            float* kdst = &Ks[r][qr * 16];
            float* vdst = &Vs[r][qr * 16];
#pragma unroll
            for (int j = 0; j < 4; j++) {
                *(float4*)&kdst[j * 4] = *(const float4*)&ksrc[j * 4];
                *(float4*)&vdst[j * 4] = *(const float4*)&vsrc[j * 4];
            }
        }
        __syncthreads();

        // S[r][c] for c in [qr*16, qr*16+16): dot(Q[r], K[c]) * scale
        float s[16];
#pragma unroll
        for (int j = 0; j < 16; j++) s[j] = 0.0f;
        const int cbase = qr * 16;
        for (int d = 0; d < 64; d += 4) {
            float4 qv = *(const float4*)&Qs[r][d];
#pragma unroll
            for (int j = 0; j < 16; j++) {
                float4 kv = *(const float4*)&Ks[cbase + j][d];
                s[j] += qv.x * kv.x + qv.y * kv.y + qv.z * kv.z + qv.w * kv.w;
            }
        }
#pragma unroll
        for (int j = 0; j < 16; j++) s[j] *= scale;

        // Row max (across the 4 quarters)
        float lm = s[0];
#pragma unroll
        for (int j = 1; j < 16; j++) lm = fmaxf(lm, s[j]);
        redmax[r][qr] = lm;
        __syncthreads();
        float m_tile = fmaxf(fmaxf(redmax[r][0], redmax[r][1]),
                             fmaxf(redmax[r][2], redmax[r][3]));
        float m_new = fmaxf(m_run, m_tile);

        // exponentials + row sum, write P tile
        float lsum = 0.0f;
#pragma unroll
        for (int j = 0; j < 16; j++) {
            float p = expf(s[j] - m_new);
            lsum += p;
            Ps[r][cbase + j] = p;
        }
        redsum[r][qr] = lsum;
        __syncthreads();
        float l_tile = redsum[r][0] + redsum[r][1] + redsum[r][2] + redsum[r][3];
        float factor = expf(m_run - m_new);   // exp(-inf)=0 on first tile
        m_run = m_new;
        l_run = l_run * factor + l_tile;

        // rescale O accumulators and accumulate P @ V for this thread's 16 dims
#pragma unroll
        for (int j = 0; j < 16; j++) oacc[j] *= factor;

        const int dbase = qr * 16;
        for (int c = 0; c < 64; c++) {
            float p = Ps[r][c];
            const float* vrow = &Vs[c][dbase];
#pragma unroll
            for (int dd = 0; dd < 16; dd += 4) {
                float4 vv = *(const float4*)&vrow[dd];
                oacc[dd + 0] += p * vv.x;
                oacc[dd + 1] += p * vv.y;
                oacc[dd + 2] += p * vv.z;
                oacc[dd + 3] += p * vv.w;
            }
        }
    }

    // normalize + write
    const float inv_l = 1.0f / l_run;
    float* dst = &O[(q0 + r) * HDIM + hof + qr * 16];
#pragma unroll
    for (int j = 0; j < 16; j += 4) {
        float4 o;
        o.x = oacc[j + 0] * inv_l;
        o.y = oacc[j + 1] * inv_l;
        o.z = oacc[j + 2] * inv_l;
        o.w = oacc[j + 3] * inv_l;
        *(float4*)&dst[j] = o;
    }
}

// ---------------------------------------------------------------------------
extern "C" void kernel_launch(void* const* d_in, const int* in_sizes, int n_in,
                              void* d_out, int out_size) {
    const float* x  = (const float*)d_in[0];
    const float* Wq = (const float*)d_in[1];
    const float* bq = (const float*)d_in[2];
    const float* Wk = (const float*)d_in[3];
    const float* bk = (const float*)d_in[4];
    const float* Wv = (const float*)d_in[5];
    const float* bv = (const float*)d_in[6];
    const float* Wo = (const float*)d_in[7];
    const float* bo = (const float*)d_in[8];
    float* out = (float*)d_out;

    float *q, *k, *v, *attn;
    cudaGetSymbolAddress((void**)&q,    g_q);
    cudaGetSymbolAddress((void**)&k,    g_k);
    cudaGetSymbolAddress((void**)&v,    g_v);
    cudaGetSymbolAddress((void**)&attn, g_attn);

    dim3 blk(256);
    dim3 grd(HDIM / 64, TSEQ / 64);

    // QKV projections
    sgemm_bias_kernel<<<grd, blk>>>(x, Wq, bq, q, TSEQ, HDIM, DEMB);
    sgemm_bias_kernel<<<grd, blk>>>(x, Wk, bk, k, TSEQ, HDIM, DEMB);
    sgemm_bias_kernel<<<grd, blk>>>(x, Wv, bv, v, TSEQ, HDIM, DEMB);

    // RoPE on Q and K
    rotary_kernel<<<TSEQ, 512>>>(q, k);

    // Flash attention
    const int smem_bytes = 4 * 64 * SMEM_STRIDE * (int)sizeof(float);  // 69632
    cudaFuncSetAttribute(flash_attn_kernel,
                         cudaFuncAttributeMaxDynamicSharedMemorySize, smem_bytes);
    flash_attn_kernel<<<dim3(TSEQ / 64, NHEADS), 256, smem_bytes>>>(q, k, v, attn);

    // Output projection
    sgemm_bias_kernel<<<grd, blk>>>(attn, Wo, bo, out, TSEQ, HDIM, HDIM);
}

// round 2
// speedup vs baseline: 11.9834x; 11.9834x over previous
#include <cuda_runtime.h>
#include <math.h>
#include <stdint.h>

#define TSEQ   4096
#define DEMB   1024
#define NHEADS 16
#define DKH    64
#define HDIM   1024

// Scratch (allocation-free rule: __device__ globals)
__device__ float g_q[TSEQ * HDIM];
__device__ float g_k[TSEQ * HDIM];
__device__ float g_v[TSEQ * HDIM];
__device__ float g_attn[TSEQ * HDIM];

__device__ __forceinline__ uint32_t f2tf(float x) {
    uint32_t r;
    asm("cvt.rna.tf32.f32 %0, %1;" : "=r"(r) : "f"(x));
    return r;
}

__device__ __forceinline__ void mma_tf32(float c[4], const uint32_t a[4], const uint32_t b[2]) {
    asm volatile(
        "mma.sync.aligned.m16n8k8.row.col.f32.tf32.tf32.f32 "
        "{%0,%1,%2,%3},{%4,%5,%6,%7},{%8,%9},{%0,%1,%2,%3};\n"
        : "+f"(c[0]), "+f"(c[1]), "+f"(c[2]), "+f"(c[3])
        : "r"(a[0]), "r"(a[1]), "r"(a[2]), "r"(a[3]), "r"(b[0]), "r"(b[1]));
}

// ---------------------------------------------------------------------------
// TF32 GEMM: C[M,N] = A[M,K] @ B[K,N] + bias.  Block 128x128, 8 warps (64x32
// each), KC=32, register-prefetch double buffering.
// Smem: As[m][k] stride 36 (frag banks 4g+t, conflict-free),
//       Bs[k][n] stride 136 (frag banks 8t+g, conflict-free).
// ---------------------------------------------------------------------------
#define AS_S 36
#define BS_S 136

__global__ __launch_bounds__(256) void gemm_tf32_kernel(
    const float* __restrict__ A, const float* __restrict__ B,
    const float* __restrict__ bias, float* __restrict__ C,
    int M, int N, int K)
{
    __shared__ uint32_t As[128 * AS_S];
    __shared__ uint32_t Bs[32 * BS_S];

    const int tid  = threadIdx.x;
    const int lane = tid & 31;
    const int wid  = tid >> 5;
    const int g    = lane >> 2;
    const int t    = lane & 3;
    const int wm   = (wid >> 2) * 64;   // warp row offset in 128
    const int wn   = (wid & 3) * 32;    // warp col offset in 128
    const int gm   = blockIdx.y * 128;
    const int gn   = blockIdx.x * 128;

    // staging indices
    const int ar  = tid >> 3;   // 0..31  (A rows ar + 32*i)
    const int ac4 = tid & 7;    // 0..7   (A float4 col within 32)
    const int br  = tid >> 5;   // 0..7   (B rows br + 8*i)
    const int bc4 = tid & 31;   // 0..31  (B float4 col within 128)

    float4 ra[4], rb[4];
    float acc[4][4][4];
#pragma unroll
    for (int i = 0; i < 4; i++)
#pragma unroll
        for (int j = 0; j < 4; j++)
#pragma unroll
            for (int e = 0; e < 4; e++) acc[i][j][e] = 0.0f;

    const int nk = K / 32;

    // prologue: load chunk 0
#pragma unroll
    for (int i = 0; i < 4; i++)
        ra[i] = *(const float4*)&A[(gm + ar + 32 * i) * K + ac4 * 4];
#pragma unroll
    for (int i = 0; i < 4; i++)
        rb[i] = *(const float4*)&B[(br + 8 * i) * N + gn + bc4 * 4];

#pragma unroll 1
    for (int kc = 0; kc < nk; kc++) {
        // store staged regs to smem (with tf32 conversion)
#pragma unroll
        for (int i = 0; i < 4; i++) {
            uint4 u;
            u.x = f2tf(ra[i].x); u.y = f2tf(ra[i].y);
            u.z = f2tf(ra[i].z); u.w = f2tf(ra[i].w);
            *(uint4*)&As[(ar + 32 * i) * AS_S + ac4 * 4] = u;
        }
#pragma unroll
        for (int i = 0; i < 4; i++) {
            uint4 u;
            u.x = f2tf(rb[i].x); u.y = f2tf(rb[i].y);
            u.z = f2tf(rb[i].z); u.w = f2tf(rb[i].w);
            *(uint4*)&Bs[(br + 8 * i) * BS_S + bc4 * 4] = u;
        }
        __syncthreads();

        // prefetch next chunk into registers
        if (kc + 1 < nk) {
            const int k0 = (kc + 1) * 32;
#pragma unroll
            for (int i = 0; i < 4; i++)
                ra[i] = *(const float4*)&A[(gm + ar + 32 * i) * K + k0 + ac4 * 4];
#pragma unroll
            for (int i = 0; i < 4; i++)
                rb[i] = *(const float4*)&B[(k0 + br + 8 * i) * N + gn + bc4 * 4];
        }

        // compute on current chunk
#pragma unroll
        for (int kk = 0; kk < 32; kk += 8) {
            uint32_t af[4][4], bf[4][2];
#pragma unroll
            for (int i = 0; i < 4; i++) {
                const int r0 = wm + i * 16 + g;
                af[i][0] = As[r0 * AS_S + kk + t];
                af[i][1] = As[(r0 + 8) * AS_S + kk + t];
                af[i][2] = As[r0 * AS_S + kk + t + 4];
                af[i][3] = As[(r0 + 8) * AS_S + kk + t + 4];
            }
#pragma unroll
            for (int j = 0; j < 4; j++) {
                const int cn = wn + j * 8 + g;
                bf[j][0] = Bs[(kk + t) * BS_S + cn];
                bf[j][1] = Bs[(kk + t + 4) * BS_S + cn];
            }
#pragma unroll
            for (int i = 0; i < 4; i++)
#pragma unroll
                for (int j = 0; j < 4; j++)
                    mma_tf32(acc[i][j], af[i], bf[j]);
        }
        __syncthreads();
    }

    // epilogue
#pragma unroll
    for (int i = 0; i < 4; i++) {
        const int row0 = gm + wm + i * 16 + g;
#pragma unroll
        for (int j = 0; j < 4; j++) {
            const int col = gn + wn + j * 8 + 2 * t;
            const float2 bv = *(const float2*)&bias[col];
            float2 o0, o1;
            o0.x = acc[i][j][0] + bv.x;  o0.y = acc[i][j][1] + bv.y;
            o1.x = acc[i][j][2] + bv.x;  o1.y = acc[i][j][3] + bv.y;
            *(float2*)&C[row0 * N + col]       = o0;
            *(float2*)&C[(row0 + 8) * N + col] = o1;
        }
    }
}

// ---------------------------------------------------------------------------
// RoPE applied in-place to Q and K (fp32, before flash staging).
// ---------------------------------------------------------------------------
__global__ void rotary_kernel(float* __restrict__ q, float* __restrict__ k) {
    const int t   = blockIdx.x;
    const int tid = threadIdx.x;           // 0..511
    const int h   = tid >> 5;
    const int i   = tid & 31;

    const float inv = exp2f(-(float)i * 0.4152410118609203f); // 10000^(-i/32)
    const float f   = (float)t * inv;
    float s, c;
    sincosf(f, &s, &c);

    const int base = t * HDIM + h * DKH;
    float q1 = q[base + i], q2 = q[base + i + 32];
    q[base + i]      = q1 * c - q2 * s;
    q[base + i + 32] = q2 * c + q1 * s;
    float k1 = k[base + i], k2 = k[base + i + 32];
    k[base + i]      = k1 * c - k2 * s;
    k[base + i + 32] = k2 * c + k1 * s;
}

// ---------------------------------------------------------------------------
// Flash attention with tf32 MMA. Block = (qtile 64 rows, head), 4 warps.
// Warp w owns q rows [w*16, w*16+16). Online softmax on MMA C-fragments,
// P round-tripped through smem (tf32) for the PV MMA.
// Smem strides: Qs/Ks/Ps 68 (banks 4g+t), Vs 72 (banks 8t+g) — conflict-free.
// ---------------------------------------------------------------------------
#define QS_S 68
#define KS_S 68
#define VS_S 72
#define PS_S 68

__global__ __launch_bounds__(128) void flash_tf32_kernel(
    const float* __restrict__ Q, const float* __restrict__ K,
    const float* __restrict__ V, float* __restrict__ O)
{
    extern __shared__ uint32_t sm[];
    uint32_t* Qs = sm;                        // 64*68
    uint32_t* Ks = Qs + 64 * QS_S;            // 64*68
    uint32_t* Vs = Ks + 64 * KS_S;            // 64*72
    uint32_t* Ps = Vs + 64 * VS_S;            // 64*68

    const int h    = blockIdx.y;
    const int q0   = blockIdx.x * 64;
    const int tid  = threadIdx.x;
    const int lane = tid & 31;
    const int wid  = tid >> 5;
    const int g    = lane >> 2;
    const int t    = lane & 3;
    const int wm   = wid * 16;
    const int hof  = h * DKH;

    // stage Q (pre-scaled by 1/sqrt(64)=0.125), tf32
    {
#pragma unroll
        for (int i = 0; i < 8; i++) {
            const int idx = tid + 128 * i;       // 0..1023
            const int r   = idx >> 4;
            const int c4  = idx & 15;
            float4 v = *(const float4*)&Q[(q0 + r) * HDIM + hof + c4 * 4];
            uint4 u;
            u.x = f2tf(v.x * 0.125f); u.y = f2tf(v.y * 0.125f);
            u.z = f2tf(v.z * 0.125f); u.w = f2tf(v.w * 0.125f);
            *(uint4*)&Qs[r * QS_S + c4 * 4] = u;
        }
    }

    float o[8][4];
#pragma unroll
    for (int j = 0; j < 8; j++)
#pragma unroll
        for (int e = 0; e < 4; e++) o[j][e] = 0.0f;
    float m0 = -INFINITY, m1 = -INFINITY;
    float l0 = 0.0f, l1 = 0.0f;

    for (int kv0 = 0; kv0 < TSEQ; kv0 += 64) {
        __syncthreads();   // previous iteration done reading Ks/Vs

        // stage K, V tiles (tf32)
#pragma unroll
        for (int i = 0; i < 8; i++) {
            const int idx = tid + 128 * i;
            const int r   = idx >> 4;
            const int c4  = idx & 15;
            float4 kv = *(const float4*)&K[(kv0 + r) * HDIM + hof + c4 * 4];
            float4 vv = *(const float4*)&V[(kv0 + r) * HDIM + hof + c4 * 4];
            uint4 uk, uv;
            uk.x = f2tf(kv.x); uk.y = f2tf(kv.y); uk.z = f2tf(kv.z); uk.w = f2tf(kv.w);
            uv.x = f2tf(vv.x); uv.y = f2tf(vv.y); uv.z = f2tf(vv.z); uv.w = f2tf(vv.w);
            *(uint4*)&Ks[r * KS_S + c4 * 4] = uk;
            *(uint4*)&Vs[r * VS_S + c4 * 4] = uv;
        }
        __syncthreads();

        // S = Q @ K^T (scaled), per warp 16x64
        float s[8][4];
#pragma unroll
        for (int j = 0; j < 8; j++)
#pragma unroll
            for (int e = 0; e < 4; e++) s[j][e] = 0.0f;

#pragma unroll
        for (int kk = 0; kk < 64; kk += 8) {
            uint32_t a[4];
            const int r0 = wm + g;
            a[0] = Qs[r0 * QS_S + kk + t];
            a[1] = Qs[(r0 + 8) * QS_S + kk + t];
            a[2] = Qs[r0 * QS_S + kk + t + 4];
            a[3] = Qs[(r0 + 8) * QS_S + kk + t + 4];
#pragma unroll
            for (int j = 0; j < 8; j++) {
                uint32_t b[2];
                const int kr = j * 8 + g;
                b[0] = Ks[kr * KS_S + kk + t];
                b[1] = Ks[kr * KS_S + kk + t + 4];
                mma_tf32(s[j], a, b);
            }
        }

        // online softmax (rows wm+g and wm+g+8)
        float mx0 = -INFINITY, mx1 = -INFINITY;
#pragma unroll
        for (int j = 0; j < 8; j++) {
            mx0 = fmaxf(mx0, fmaxf(s[j][0], s[j][1]));
            mx1 = fmaxf(mx1, fmaxf(s[j][2], s[j][3]));
        }
        mx0 = fmaxf(mx0, __shfl_xor_sync(0xffffffffu, mx0, 1));
        mx0 = fmaxf(mx0, __shfl_xor_sync(0xffffffffu, mx0, 2));
        mx1 = fmaxf(mx1, __shfl_xor_sync(0xffffffffu, mx1, 1));
        mx1 = fmaxf(mx1, __shfl_xor_sync(0xffffffffu, mx1, 2));

        const float mn0 = fmaxf(m0, mx0);
        const float mn1 = fmaxf(m1, mx1);
        const float f0  = __expf(m0 - mn0);
        const float f1  = __expf(m1 - mn1);

        float ls0 = 0.0f, ls1 = 0.0f;
#pragma unroll
        for (int j = 0; j < 8; j++) {
            s[j][0] = __expf(s[j][0] - mn0);
            s[j][1] = __expf(s[j][1] - mn0);
            s[j][2] = __expf(s[j][2] - mn1);
            s[j][3] = __expf(s[j][3] - mn1);
            ls0 += s[j][0] + s[j][1];
            ls1 += s[j][2] + s[j][3];
        }
        ls0 += __shfl_xor_sync(0xffffffffu, ls0, 1);
        ls0 += __shfl_xor_sync(0xffffffffu, ls0, 2);
        ls1 += __shfl_xor_sync(0xffffffffu, ls1, 1);
        ls1 += __shfl_xor_sync(0xffffffffu, ls1, 2);

        l0 = l0 * f0 + ls0;
        l1 = l1 * f1 + ls1;
        m0 = mn0;  m1 = mn1;

        // rescale O accumulators
#pragma unroll
        for (int j = 0; j < 8; j++) {
            o[j][0] *= f0; o[j][1] *= f0;
            o[j][2] *= f1; o[j][3] *= f1;
        }

        // write P (tf32) to smem — warp-local region, only __syncwarp needed
#pragma unroll
        for (int j = 0; j < 8; j++) {
            const int col = j * 8 + 2 * t;
            uint2 u0, u1;
            u0.x = f2tf(s[j][0]); u0.y = f2tf(s[j][1]);
            u1.x = f2tf(s[j][2]); u1.y = f2tf(s[j][3]);
            *(uint2*)&Ps[(wm + g) * PS_S + col]     = u0;
            *(uint2*)&Ps[(wm + g + 8) * PS_S + col] = u1;
        }
        __syncwarp();

        // O += P @ V
#pragma unroll
        for (int kv = 0; kv < 64; kv += 8) {
            uint32_t a[4];
            const int r0 = wm + g;
            a[0] = Ps[r0 * PS_S + kv + t];
            a[1] = Ps[(r0 + 8) * PS_S + kv + t];
            a[2] = Ps[r0 * PS_S + kv + t + 4];
            a[3] = Ps[(r0 + 8) * PS_S + kv + t + 4];
#pragma unroll
            for (int jd = 0; jd < 8; jd++) {
                uint32_t b[2];
                b[0] = Vs[(kv + t) * VS_S + jd * 8 + g];
                b[1] = Vs[(kv + t + 4) * VS_S + jd * 8 + g];
                mma_tf32(o[jd], a, b);
            }
        }
    }

    // normalize + write out
    const float inv0 = 1.0f / l0;
    const float inv1 = 1.0f / l1;
    const int row0 = q0 + wm + g;
#pragma unroll
    for (int jd = 0; jd < 8; jd++) {
        const int col = hof + jd * 8 + 2 * t;
        float2 v0, v1;
        v0.x = o[jd][0] * inv0;  v0.y = o[jd][1] * inv0;
        v1.x = o[jd][2] * inv1;  v1.y = o[jd][3] * inv1;
        *(float2*)&O[row0 * HDIM + col]       = v0;
        *(float2*)&O[(row0 + 8) * HDIM + col] = v1;
    }
}

// ---------------------------------------------------------------------------
extern "C" void kernel_launch(void* const* d_in, const int* in_sizes, int n_in,
                              void* d_out, int out_size) {
    const float* x  = (const float*)d_in[0];
    const float* Wq = (const float*)d_in[1];
    const float* bq = (const float*)d_in[2];
    const float* Wk = (const float*)d_in[3];
    const float* bk = (const float*)d_in[4];
    const float* Wv = (const float*)d_in[5];
    const float* bv = (const float*)d_in[6];
    const float* Wo = (const float*)d_in[7];
    const float* bo = (const float*)d_in[8];
    float* out = (float*)d_out;

    float *q, *k, *v, *attn;
    cudaGetSymbolAddress((void**)&q,    g_q);
    cudaGetSymbolAddress((void**)&k,    g_k);
    cudaGetSymbolAddress((void**)&v,    g_v);
    cudaGetSymbolAddress((void**)&attn, g_attn);

    dim3 blk(256);
    dim3 grd(HDIM / 128, TSEQ / 128);   // (8, 32)

    // QKV projections (tf32 MMA)
    gemm_tf32_kernel<<<grd, blk>>>(x, Wq, bq, q, TSEQ, HDIM, DEMB);
    gemm_tf32_kernel<<<grd, blk>>>(x, Wk, bk, k, TSEQ, HDIM, DEMB);
    gemm_tf32_kernel<<<grd, blk>>>(x, Wv, bv, v, TSEQ, HDIM, DEMB);

    // RoPE on Q and K (fp32)
    rotary_kernel<<<TSEQ, 512>>>(q, k);

    // Flash attention (tf32 MMA)
    const int smem_bytes = (64 * QS_S + 64 * KS_S + 64 * VS_S + 64 * PS_S) * (int)sizeof(uint32_t);
    cudaFuncSetAttribute(flash_tf32_kernel,
                         cudaFuncAttributeMaxDynamicSharedMemorySize, smem_bytes);
    flash_tf32_kernel<<<dim3(TSEQ / 64, NHEADS), 128, smem_bytes>>>(q, k, v, attn);

    // Output projection
    gemm_tf32_kernel<<<grd, blk>>>(attn, Wo, bo, out, TSEQ, HDIM, HDIM);
}

// round 3
// speedup vs baseline: 24.8929x; 2.0773x over previous
#include <cuda_runtime.h>
#include <cuda_fp16.h>
#include <math.h>
#include <stdint.h>

#define TSEQ   4096
#define DEMB   1024
#define NHEADS 16
#define DKH    64
#define HDIM   1024

// Scratch (allocation-free rule: __device__ globals)
__device__ float    g_q[TSEQ * HDIM];      // Q fp32 (rotary in reads)
__device__ float    g_k[TSEQ * HDIM];      // K fp32 (rotary in reads)
__device__ float    g_v[TSEQ * HDIM];      // V fp32
__device__ uint32_t g_qh[TSEQ * HDIM / 2]; // Q fp16 packed (pre-scaled by 0.125)
__device__ uint32_t g_kh[TSEQ * HDIM / 2]; // K fp16 packed
__device__ uint32_t g_vh[TSEQ * HDIM / 2]; // V fp16 packed
__device__ float    g_attn[TSEQ * HDIM];

__device__ __forceinline__ uint32_t pack2(float lo, float hi) {
    __half2 h = __floats2half2_rn(lo, hi);   // .x = lo (low 16 bits)
    return *(uint32_t*)&h;
}

__device__ __forceinline__ void mma_f16(float c[4], const uint32_t a[4], const uint32_t b[2]) {
    asm volatile(
        "mma.sync.aligned.m16n8k16.row.col.f32.f16.f16.f32 "
        "{%0,%1,%2,%3},{%4,%5,%6,%7},{%8,%9},{%0,%1,%2,%3};\n"
        : "+f"(c[0]), "+f"(c[1]), "+f"(c[2]), "+f"(c[3])
        : "r"(a[0]), "r"(a[1]), "r"(a[2]), "r"(a[3]), "r"(b[0]), "r"(b[1]));
}

__device__ __forceinline__ void ldsm_x4_t(uint32_t& r0, uint32_t& r1, uint32_t& r2, uint32_t& r3,
                                          const void* p) {
    uint32_t addr = (uint32_t)__cvta_generic_to_shared(p);
    asm volatile("ldmatrix.sync.aligned.m8n8.x4.trans.shared.b16 {%0,%1,%2,%3}, [%4];"
                 : "=r"(r0), "=r"(r1), "=r"(r2), "=r"(r3) : "r"(addr));
}

// ---------------------------------------------------------------------------
// FP16 GEMM: C = A[M,K] @ B[K,N] + bias. Block 128x128, 8 warps (64x32), KC=32.
// As[m][k]: 40 halves/row (20 u32) -> A-frag LDS.32 conflict-free (4g+t).
// Bs[k][n]: 136 halves/row (68 u32) -> ldmatrix.trans conflict-free (16k mod 128).
// ---------------------------------------------------------------------------
#define GAS 20   // A row stride in u32
#define GBS 68   // B row stride in u32

__global__ __launch_bounds__(256) void gemm_f16_kernel(
    const float* __restrict__ A, const float* __restrict__ B,
    const float* __restrict__ bias, float* __restrict__ C,
    int M, int N, int K)
{
    __shared__ uint32_t As[128 * GAS];
    __shared__ uint32_t Bs[32 * GBS];

    const int tid  = threadIdx.x;
    const int lane = tid & 31;
    const int wid  = tid >> 5;
    const int g    = lane >> 2;
    const int t    = lane & 3;
    const int wm   = (wid >> 2) * 64;
    const int wn   = (wid & 3) * 32;
    const int gm   = blockIdx.y * 128;
    const int gn   = blockIdx.x * 128;

    const int ar  = tid >> 3;   // 0..31
    const int ac4 = tid & 7;    // 0..7
    const int br  = tid >> 5;   // 0..7
    const int bc4 = tid & 31;   // 0..31

    float4 ra[4], rb[4];
    float acc[4][4][4];
#pragma unroll
    for (int i = 0; i < 4; i++)
#pragma unroll
        for (int j = 0; j < 4; j++)
#pragma unroll
            for (int e = 0; e < 4; e++) acc[i][j][e] = 0.0f;

    const int nk = K / 32;

#pragma unroll
    for (int i = 0; i < 4; i++)
        ra[i] = *(const float4*)&A[(gm + ar + 32 * i) * K + ac4 * 4];
#pragma unroll
    for (int i = 0; i < 4; i++)
        rb[i] = *(const float4*)&B[(br + 8 * i) * N + gn + bc4 * 4];

#pragma unroll 1
    for (int kc = 0; kc < nk; kc++) {
#pragma unroll
        for (int i = 0; i < 4; i++) {
            uint2 u;
            u.x = pack2(ra[i].x, ra[i].y);
            u.y = pack2(ra[i].z, ra[i].w);
            *(uint2*)&As[(ar + 32 * i) * GAS + ac4 * 2] = u;
        }
#pragma unroll
        for (int i = 0; i < 4; i++) {
            uint2 u;
            u.x = pack2(rb[i].x, rb[i].y);
            u.y = pack2(rb[i].z, rb[i].w);
            *(uint2*)&Bs[(br + 8 * i) * GBS + bc4 * 2] = u;
        }
        __syncthreads();

        if (kc + 1 < nk) {
            const int k0 = (kc + 1) * 32;
#pragma unroll
            for (int i = 0; i < 4; i++)
                ra[i] = *(const float4*)&A[(gm + ar + 32 * i) * K + k0 + ac4 * 4];
#pragma unroll
            for (int i = 0; i < 4; i++)
                rb[i] = *(const float4*)&B[(k0 + br + 8 * i) * N + gn + bc4 * 4];
        }

#pragma unroll
        for (int kk = 0; kk < 32; kk += 16) {
            uint32_t af[4][4], bf[4][2];
#pragma unroll
            for (int i = 0; i < 4; i++) {
                const int r0 = wm + i * 16 + g;
                af[i][0] = As[r0 * GAS + (kk >> 1) + t];
                af[i][1] = As[(r0 + 8) * GAS + (kk >> 1) + t];
                af[i][2] = As[r0 * GAS + (kk >> 1) + t + 4];
                af[i][3] = As[(r0 + 8) * GAS + (kk >> 1) + t + 4];
            }
#pragma unroll
            for (int nb = 0; nb < 2; nb++) {
                const int r  = (lane & 7) | (lane & 8);         // 0..15
                const int co = (lane & 16) ? 8 : 0;
                const __half* hp = (const __half*)Bs;
                ldsm_x4_t(bf[2 * nb][0], bf[2 * nb][1], bf[2 * nb + 1][0], bf[2 * nb + 1][1],
                          &hp[(kk + r) * 136 + wn + nb * 16 + co]);
            }
#pragma unroll
            for (int i = 0; i < 4; i++)
#pragma unroll
                for (int j = 0; j < 4; j++)
                    mma_f16(acc[i][j], af[i], bf[j]);
        }
        __syncthreads();
    }

#pragma unroll
    for (int i = 0; i < 4; i++) {
        const int row0 = gm + wm + i * 16 + g;
#pragma unroll
        for (int j = 0; j < 4; j++) {
            const int col = gn + wn + j * 8 + 2 * t;
            const float2 bv = *(const float2*)&bias[col];
            float2 o0, o1;
            o0.x = acc[i][j][0] + bv.x;  o0.y = acc[i][j][1] + bv.y;
            o1.x = acc[i][j][2] + bv.x;  o1.y = acc[i][j][3] + bv.y;
            *(float2*)&C[row0 * N + col]       = o0;
            *(float2*)&C[(row0 + 8) * N + col] = o1;
        }
    }
}

// ---------------------------------------------------------------------------
// RoPE: reads fp32 Q/K, writes packed fp16 (Q pre-scaled by 0.125).
// Block 256 = (h 0..15, pair p 0..15); grid TSEQ.
// ---------------------------------------------------------------------------
__global__ void rotary_pack_kernel(const float* __restrict__ q, const float* __restrict__ k,
                                   uint32_t* __restrict__ qh, uint32_t* __restrict__ kh) {
    const int tseq = blockIdx.x;
    const int tid  = threadIdx.x;
    const int h    = tid >> 4;
    const int p    = tid & 15;

    const float inv0 = exp2f(-(float)(2 * p)     * 0.4152410118609203f);
    const float inv1 = exp2f(-(float)(2 * p + 1) * 0.4152410118609203f);
    float s0, c0, s1, c1;
    sincosf((float)tseq * inv0, &s0, &c0);
    sincosf((float)tseq * inv1, &s1, &c1);

    const int base = tseq * HDIM + h * DKH;
    float2 q1 = *(const float2*)&q[base + 2 * p];
    float2 q2 = *(const float2*)&q[base + 32 + 2 * p];
    float2 k1 = *(const float2*)&k[base + 2 * p];
    float2 k2 = *(const float2*)&k[base + 32 + 2 * p];

    const int ob = tseq * (HDIM / 2) + h * 32;
    qh[ob + p]      = pack2((q1.x * c0 - q2.x * s0) * 0.125f, (q1.y * c1 - q2.y * s1) * 0.125f);
    qh[ob + 16 + p] = pack2((q2.x * c0 + q1.x * s0) * 0.125f, (q2.y * c1 + q1.y * s1) * 0.125f);
    kh[ob + p]      = pack2(k1.x * c0 - k2.x * s0, k1.y * c1 - k2.y * s1);
    kh[ob + 16 + p] = pack2(k2.x * c0 + k1.x * s0, k2.y * c1 + k1.y * s1);
}

// fp32 -> packed fp16 (V)
__global__ void cvt_f16_kernel(const float4* __restrict__ src, uint2* __restrict__ dst, int n4) {
    const int i = blockIdx.x * blockDim.x + threadIdx.x;
    if (i < n4) {
        float4 v = src[i];
        uint2 u;
        u.x = pack2(v.x, v.y);
        u.y = pack2(v.z, v.w);
        dst[i] = u;
    }
}

// ---------------------------------------------------------------------------
// Flash attention fp16. Block = (128 q rows, head), 8 warps (16 rows each).
// Q/K/V fp16 in smem (stride 72 halves = 36 u32). P stays in registers:
// m16n8 C-fragment layout == m16n8k16 A-fragment layout after half2 packing.
// ---------------------------------------------------------------------------
#define FQS 36   // u32 row stride
#define FKS 36
#define FVS 36

__global__ __launch_bounds__(256) void flash_f16_kernel(
    const uint32_t* __restrict__ Qh, const uint32_t* __restrict__ Kh,
    const uint32_t* __restrict__ Vh, float* __restrict__ O)
{
    __shared__ uint32_t Qs[128 * FQS];
    __shared__ uint32_t Ks[64 * FKS];
    __shared__ uint32_t Vs[64 * FVS];

    const int h    = blockIdx.y;
    const int q0   = blockIdx.x * 128;
    const int tid  = threadIdx.x;
    const int lane = tid & 31;
    const int wid  = tid >> 5;
    const int g    = lane >> 2;
    const int t    = lane & 3;
    const int wm   = wid * 16;
    const int hofu = h * 32;           // head offset in u32
    const int hof  = h * DKH;          // head offset in floats

    // stage Q (fp16, already scaled): 128 rows x 8 uint4
#pragma unroll
    for (int i = 0; i < 4; i++) {
        const int idx = tid + 256 * i;
        const int r   = idx >> 3;
        const int c   = idx & 7;
        *(uint4*)&Qs[r * FQS + c * 4] =
            *(const uint4*)&Qh[(q0 + r) * (HDIM / 2) + hofu + c * 4];
    }

    float o[8][4];
#pragma unroll
    for (int j = 0; j < 8; j++)
#pragma unroll
        for (int e = 0; e < 4; e++) o[j][e] = 0.0f;
    float m0 = -INFINITY, m1 = -INFINITY;
    float l0 = 0.0f, l1 = 0.0f;

    for (int kv0 = 0; kv0 < TSEQ; kv0 += 64) {
        __syncthreads();
#pragma unroll
        for (int i = 0; i < 2; i++) {
            const int idx = tid + 256 * i;
            const int r   = idx >> 3;
            const int c   = idx & 7;
            const int go  = (kv0 + r) * (HDIM / 2) + hofu + c * 4;
            *(uint4*)&Ks[r * FKS + c * 4] = *(const uint4*)&Kh[go];
            *(uint4*)&Vs[r * FVS + c * 4] = *(const uint4*)&Vh[go];
        }
        __syncthreads();

        // S = Q @ K^T  (Q pre-scaled by 1/8)
        float s[8][4];
#pragma unroll
        for (int j = 0; j < 8; j++)
#pragma unroll
            for (int e = 0; e < 4; e++) s[j][e] = 0.0f;

#pragma unroll
        for (int kk = 0; kk < 64; kk += 16) {
            uint32_t a[4];
            const int r0 = wm + g;
            const int ku = kk >> 1;
            a[0] = Qs[r0 * FQS + ku + t];
            a[1] = Qs[(r0 + 8) * FQS + ku + t];
            a[2] = Qs[r0 * FQS + ku + t + 4];
            a[3] = Qs[(r0 + 8) * FQS + ku + t + 4];
#pragma unroll
            for (int j = 0; j < 8; j++) {
                uint32_t b[2];
                const int kr = j * 8 + g;
                b[0] = Ks[kr * FKS + ku + t];
                b[1] = Ks[kr * FKS + ku + t + 4];
                mma_f16(s[j], a, b);
            }
        }

        // online softmax (rows wm+g, wm+g+8)
        float mx0 = -INFINITY, mx1 = -INFINITY;
#pragma unroll
        for (int j = 0; j < 8; j++) {
            mx0 = fmaxf(mx0, fmaxf(s[j][0], s[j][1]));
            mx1 = fmaxf(mx1, fmaxf(s[j][2], s[j][3]));
        }
        mx0 = fmaxf(mx0, __shfl_xor_sync(0xffffffffu, mx0, 1));
        mx0 = fmaxf(mx0, __shfl_xor_sync(0xffffffffu, mx0, 2));
        mx1 = fmaxf(mx1, __shfl_xor_sync(0xffffffffu, mx1, 1));
        mx1 = fmaxf(mx1, __shfl_xor_sync(0xffffffffu, mx1, 2));

        const float mn0 = fmaxf(m0, mx0);
        const float mn1 = fmaxf(m1, mx1);
        const float f0  = __expf(m0 - mn0);
        const float f1  = __expf(m1 - mn1);

        float ls0 = 0.0f, ls1 = 0.0f;
#pragma unroll
        for (int j = 0; j < 8; j++) {
            s[j][0] = __expf(s[j][0] - mn0);
            s[j][1] = __expf(s[j][1] - mn0);
            s[j][2] = __expf(s[j][2] - mn1);
            s[j][3] = __expf(s[j][3] - mn1);
            ls0 += s[j][0] + s[j][1];
            ls1 += s[j][2] + s[j][3];
        }
        ls0 += __shfl_xor_sync(0xffffffffu, ls0, 1);
        ls0 += __shfl_xor_sync(0xffffffffu, ls0, 2);
        ls1 += __shfl_xor_sync(0xffffffffu, ls1, 1);
        ls1 += __shfl_xor_sync(0xffffffffu, ls1, 2);

        l0 = l0 * f0 + ls0;
        l1 = l1 * f1 + ls1;
        m0 = mn0;  m1 = mn1;

#pragma unroll
        for (int j = 0; j < 8; j++) {
            o[j][0] *= f0; o[j][1] *= f0;
            o[j][2] *= f1; o[j][3] *= f1;
        }

        // O += P @ V   (P from registers: C-frag == A-frag layout)
        const __half* vh = (const __half*)Vs;
        const int rl  = (lane & 7) | (lane & 8);          // 0..15
        const int col = (lane & 16) ? 8 : 0;
#pragma unroll
        for (int kk = 0; kk < 64; kk += 16) {
            const int j0 = kk >> 3;
            uint32_t a[4];
            a[0] = pack2(s[j0][0],     s[j0][1]);
            a[1] = pack2(s[j0][2],     s[j0][3]);
            a[2] = pack2(s[j0 + 1][0], s[j0 + 1][1]);
            a[3] = pack2(s[j0 + 1][2], s[j0 + 1][3]);
#pragma unroll
            for (int jd = 0; jd < 8; jd += 2) {
                uint32_t b0[2], b1[2];
                ldsm_x4_t(b0[0], b0[1], b1[0], b1[1],
                          &vh[(kk + rl) * 72 + jd * 8 + col]);
                mma_f16(o[jd],     a, b0);
                mma_f16(o[jd + 1], a, b1);
            }
        }
    }

    const float inv0 = 1.0f / l0;
    const float inv1 = 1.0f / l1;
    const int row0 = q0 + wm + g;
#pragma unroll
    for (int jd = 0; jd < 8; jd++) {
        const int col = hof + jd * 8 + 2 * t;
        float2 v0, v1;
        v0.x = o[jd][0] * inv0;  v0.y = o[jd][1] * inv0;
        v1.x = o[jd][2] * inv1;  v1.y = o[jd][3] * inv1;
        *(float2*)&O[row0 * HDIM + col]       = v0;
        *(float2*)&O[(row0 + 8) * HDIM + col] = v1;
    }
}

// ---------------------------------------------------------------------------
extern "C" void kernel_launch(void* const* d_in, const int* in_sizes, int n_in,
                              void* d_out, int out_size) {
    const float* x  = (const float*)d_in[0];
    const float* Wq = (const float*)d_in[1];
    const float* bq = (const float*)d_in[2];
    const float* Wk = (const float*)d_in[3];
    const float* bk = (const float*)d_in[4];
    const float* Wv = (const float*)d_in[5];
    const float* bv = (const float*)d_in[6];
    const float* Wo = (const float*)d_in[7];
    const float* bo = (const float*)d_in[8];
    float* out = (float*)d_out;

    float *q, *k, *v, *attn;
    uint32_t *qh, *kh, *vh;
    cudaGetSymbolAddress((void**)&q,    g_q);
    cudaGetSymbolAddress((void**)&k,    g_k);
    cudaGetSymbolAddress((void**)&v,    g_v);
    cudaGetSymbolAddress((void**)&qh,   g_qh);
    cudaGetSymbolAddress((void**)&kh,   g_kh);
    cudaGetSymbolAddress((void**)&vh,   g_vh);
    cudaGetSymbolAddress((void**)&attn, g_attn);

    dim3 blk(256);
    dim3 grd(HDIM / 128, TSEQ / 128);   // (8, 32)

    gemm_f16_kernel<<<grd, blk>>>(x, Wq, bq, q, TSEQ, HDIM, DEMB);
    gemm_f16_kernel<<<grd, blk>>>(x, Wk, bk, k, TSEQ, HDIM, DEMB);
    gemm_f16_kernel<<<grd, blk>>>(x, Wv, bv, v, TSEQ, HDIM, DEMB);

    rotary_pack_kernel<<<TSEQ, 256>>>(q, k, qh, kh);
    cvt_f16_kernel<<<(TSEQ * HDIM / 4 + 255) / 256, 256>>>((const float4*)v, (uint2*)vh,
                                                           TSEQ * HDIM / 4);

    flash_f16_kernel<<<dim3(TSEQ / 128, NHEADS), 256>>>(qh, kh, vh, attn);

    gemm_f16_kernel<<<grd, blk>>>(attn, Wo, bo, out, TSEQ, HDIM, HDIM);
}

// round 4
// speedup vs baseline: 29.7222x; 1.1940x over previous
#include <cuda_runtime.h>
#include <cuda_fp16.h>
#include <math.h>
#include <stdint.h>

#define TSEQ   4096
#define DEMB   1024
#define NHEADS 16
#define DKH    64
#define HDIM   1024

// Scratch (allocation-free rule: __device__ globals)
__device__ float    g_q[TSEQ * HDIM];          // Q fp32 (pre-rotary)
__device__ float    g_k[TSEQ * HDIM];          // K fp32 (pre-rotary)
__device__ uint32_t g_xh[TSEQ * DEMB / 2];     // x fp16
__device__ uint32_t g_wqh[DEMB * HDIM / 2];    // weights fp16
__device__ uint32_t g_wkh[DEMB * HDIM / 2];
__device__ uint32_t g_wvh[DEMB * HDIM / 2];
__device__ uint32_t g_woh[HDIM * HDIM / 2];
__device__ uint32_t g_qh[TSEQ * HDIM / 2];     // rotary Q fp16 (pre-scaled 0.125)
__device__ uint32_t g_kh[TSEQ * HDIM / 2];     // rotary K fp16
__device__ uint32_t g_vh[TSEQ * HDIM / 2];     // V fp16
__device__ uint32_t g_ah[TSEQ * HDIM / 2];     // attn out fp16

__device__ __forceinline__ uint32_t pack2(float lo, float hi) {
    __half2 h = __floats2half2_rn(lo, hi);
    return *(uint32_t*)&h;
}

__device__ __forceinline__ void mma_f16(float c[4], const uint32_t a[4], const uint32_t b[2]) {
    asm volatile(
        "mma.sync.aligned.m16n8k16.row.col.f32.f16.f16.f32 "
        "{%0,%1,%2,%3},{%4,%5,%6,%7},{%8,%9},{%0,%1,%2,%3};\n"
        : "+f"(c[0]), "+f"(c[1]), "+f"(c[2]), "+f"(c[3])
        : "r"(a[0]), "r"(a[1]), "r"(a[2]), "r"(a[3]), "r"(b[0]), "r"(b[1]));
}

__device__ __forceinline__ void ldsm_x4(uint32_t& r0, uint32_t& r1, uint32_t& r2, uint32_t& r3,
                                        uint32_t addr) {
    asm volatile("ldmatrix.sync.aligned.m8n8.x4.shared.b16 {%0,%1,%2,%3}, [%4];"
                 : "=r"(r0), "=r"(r1), "=r"(r2), "=r"(r3) : "r"(addr));
}

__device__ __forceinline__ void ldsm_x4_t(uint32_t& r0, uint32_t& r1, uint32_t& r2, uint32_t& r3,
                                          uint32_t addr) {
    asm volatile("ldmatrix.sync.aligned.m8n8.x4.trans.shared.b16 {%0,%1,%2,%3}, [%4];"
                 : "=r"(r0), "=r"(r1), "=r"(r2), "=r"(r3) : "r"(addr));
}

__device__ __forceinline__ void cp16(uint32_t smem, const void* gmem) {
    asm volatile("cp.async.cg.shared.global [%0], [%1], 16;\n" :: "r"(smem), "l"(gmem));
}
__device__ __forceinline__ void cp_commit() {
    asm volatile("cp.async.commit_group;\n");
}
template <int N> __device__ __forceinline__ void cp_wait() {
    asm volatile("cp.async.wait_group %0;\n" :: "n"(N));
}

// fp32 -> packed fp16
__global__ void cvt_f16_kernel(const float4* __restrict__ src, uint2* __restrict__ dst, int n4) {
    const int i = blockIdx.x * blockDim.x + threadIdx.x;
    if (i < n4) {
        float4 v = src[i];
        uint2 u;
        u.x = pack2(v.x, v.y);
        u.y = pack2(v.z, v.w);
        dst[i] = u;
    }
}

// ---------------------------------------------------------------------------
// FP16 GEMM: C = A[M,K]fp16 @ B[K,N]fp16 + bias(f32). Block 128x128, 8 warps
// (64x32 each), BK=64, 3-stage cp.async ring, SW128 XOR swizzle, ldmatrix.
// Smem/stage: A 128x128B (16KB) + B 64x256B (16KB) = 32KB; 3 stages = 96KB.
// ---------------------------------------------------------------------------
template <bool OUT_HALF>
__global__ __launch_bounds__(256) void gemm_f16_kernel(
    const __half* __restrict__ A, const __half* __restrict__ B,
    const float* __restrict__ bias, void* __restrict__ Cout,
    int M, int N, int K)
{
    extern __shared__ char smem[];
    const uint32_t sbase = (uint32_t)__cvta_generic_to_shared(smem);

    const int tid  = threadIdx.x;
    const int lane = tid & 31;
    const int wid  = tid >> 5;
    const int g    = lane >> 2;
    const int t    = lane & 3;
    const int wm   = (wid >> 2) * 64;
    const int wn   = (wid & 3) * 32;
    const int gm   = blockIdx.y * 128;
    const int gn   = blockIdx.x * 128;
    const int nk   = K >> 6;

    float acc[4][4][4];
#pragma unroll
    for (int i = 0; i < 4; i++)
#pragma unroll
        for (int j = 0; j < 4; j++)
#pragma unroll
            for (int e = 0; e < 4; e++) acc[i][j][e] = 0.0f;

    auto issue = [&](int kc, int st) {
        const uint32_t sa = sbase + st * 32768;
#pragma unroll
        for (int i = 0; i < 4; i++) {
            const int idx = tid + 256 * i;
            const int r = idx >> 3, c = idx & 7;
            cp16(sa + r * 128 + ((c ^ (r & 7)) << 4),
                 A + (size_t)(gm + r) * K + kc * 64 + c * 8);
        }
#pragma unroll
        for (int i = 0; i < 4; i++) {
            const int idx = tid + 256 * i;
            const int r = idx >> 4, c = idx & 15;
            cp16(sa + 16384 + r * 256 + ((c ^ (r & 7)) << 4),
                 B + (size_t)(kc * 64 + r) * N + gn + c * 8);
        }
        cp_commit();
    };

    issue(0, 0);
    issue(1, 1);

#pragma unroll 1
    for (int kc = 0; kc < nk; kc++) {
        if (kc < nk - 1) cp_wait<1>(); else cp_wait<0>();
        __syncthreads();
        if (kc + 2 < nk) issue(kc + 2, (kc + 2) % 3);

        const uint32_t sa = sbase + (kc % 3) * 32768;
#pragma unroll
        for (int kk = 0; kk < 64; kk += 16) {
            uint32_t af[4][4], bf[4][2];
#pragma unroll
            for (int i = 0; i < 4; i++) {
                const int row = wm + i * 16 + (lane & 15);
                const int ch  = (kk >> 3) + (lane >> 4);
                ldsm_x4(af[i][0], af[i][1], af[i][2], af[i][3],
                        sa + row * 128 + ((ch ^ (row & 7)) << 4));
            }
#pragma unroll
            for (int nb = 0; nb < 2; nb++) {
                const int row = kk + ((lane & 7) | (lane & 8));
                const int ch  = ((wn + nb * 16) >> 3) + ((lane >> 4) & 1);
                ldsm_x4_t(bf[2 * nb][0], bf[2 * nb][1], bf[2 * nb + 1][0], bf[2 * nb + 1][1],
                          sa + 16384 + row * 256 + ((ch ^ (row & 7)) << 4));
            }
#pragma unroll
            for (int i = 0; i < 4; i++)
#pragma unroll
                for (int j = 0; j < 4; j++)
                    mma_f16(acc[i][j], af[i], bf[j]);
        }
    }

#pragma unroll
    for (int i = 0; i < 4; i++) {
        const int row0 = gm + wm + i * 16 + g;
#pragma unroll
        for (int j = 0; j < 4; j++) {
            const int col = gn + wn + j * 8 + 2 * t;
            const float2 bv = *(const float2*)&bias[col];
            if (OUT_HALF) {
                uint32_t* C = (uint32_t*)Cout;
                C[(row0 * N + col) >> 1]       = pack2(acc[i][j][0] + bv.x, acc[i][j][1] + bv.y);
                C[((row0 + 8) * N + col) >> 1] = pack2(acc[i][j][2] + bv.x, acc[i][j][3] + bv.y);
            } else {
                float* C = (float*)Cout;
                float2 o0, o1;
                o0.x = acc[i][j][0] + bv.x;  o0.y = acc[i][j][1] + bv.y;
                o1.x = acc[i][j][2] + bv.x;  o1.y = acc[i][j][3] + bv.y;
                *(float2*)&C[row0 * N + col]       = o0;
                *(float2*)&C[(row0 + 8) * N + col] = o1;
            }
        }
    }
}

// ---------------------------------------------------------------------------
// RoPE: reads fp32 Q/K, writes packed fp16 (Q pre-scaled by 0.125).
// ---------------------------------------------------------------------------
__global__ void rotary_pack_kernel(const float* __restrict__ q, const float* __restrict__ k,
                                   uint32_t* __restrict__ qh, uint32_t* __restrict__ kh) {
    const int tseq = blockIdx.x;
    const int tid  = threadIdx.x;
    const int h    = tid >> 4;
    const int p    = tid & 15;

    const float inv0 = exp2f(-(float)(2 * p)     * 0.4152410118609203f);
    const float inv1 = exp2f(-(float)(2 * p + 1) * 0.4152410118609203f);
    float s0, c0, s1, c1;
    sincosf((float)tseq * inv0, &s0, &c0);
    sincosf((float)tseq * inv1, &s1, &c1);

    const int base = tseq * HDIM + h * DKH;
    float2 q1 = *(const float2*)&q[base + 2 * p];
    float2 q2 = *(const float2*)&q[base + 32 + 2 * p];
    float2 k1 = *(const float2*)&k[base + 2 * p];
    float2 k2 = *(const float2*)&k[base + 32 + 2 * p];

    const int ob = tseq * (HDIM / 2) + h * 32;
    qh[ob + p]      = pack2((q1.x * c0 - q2.x * s0) * 0.125f, (q1.y * c1 - q2.y * s1) * 0.125f);
    qh[ob + 16 + p] = pack2((q2.x * c0 + q1.x * s0) * 0.125f, (q2.y * c1 + q1.y * s1) * 0.125f);
    kh[ob + p]      = pack2(k1.x * c0 - k2.x * s0, k1.y * c1 - k2.y * s1);
    kh[ob + 16 + p] = pack2(k2.x * c0 + k1.x * s0, k2.y * c1 + k1.y * s1);
}

// ---------------------------------------------------------------------------
// Flash attention fp16. Block = (128 q rows, head), 8 warps (16 rows each).
// Q tile resident (16KB); K/V 64-key tiles in a 3-stage cp.async ring
// (16KB/stage). SW128 swizzle + ldmatrix.x4 everywhere. Writes fp16 attn.
// Smem: 16KB + 3*16KB = 64KB dynamic.
// ---------------------------------------------------------------------------
__global__ __launch_bounds__(256) void flash_f16_kernel(
    const __half* __restrict__ Qh, const __half* __restrict__ Kh,
    const __half* __restrict__ Vh, uint32_t* __restrict__ Oh)
{
    extern __shared__ char smem[];
    const uint32_t sbase = (uint32_t)__cvta_generic_to_shared(smem);

    const int h    = blockIdx.y;
    const int q0   = blockIdx.x * 128;
    const int tid  = threadIdx.x;
    const int lane = tid & 31;
    const int wid  = tid >> 5;
    const int g    = lane >> 2;
    const int t    = lane & 3;
    const int wm   = wid * 16;
    const int ntiles = TSEQ / 64;

    auto issueKV = (void*)0;  // (placeholder to keep structure obvious)

    // prologue: Q + tile0 as group0, tile1 as group1
    {
#pragma unroll
        for (int i = 0; i < 4; i++) {
            const int idx = tid + 256 * i;
            const int r = idx >> 3, c = idx & 7;
            cp16(sbase + r * 128 + ((c ^ (r & 7)) << 4),
                 Qh + (size_t)(q0 + r) * HDIM + h * DKH + c * 8);
        }
    }

    auto issue_tile = [&](int tile, int st) {
        const uint32_t kb = sbase + 16384 + st * 16384;
        const int kv0 = tile * 64;
#pragma unroll
        for (int i = 0; i < 2; i++) {
            const int idx = tid + 256 * i;
            const int r = idx >> 3, c = idx & 7;
            const uint32_t off = r * 128 + ((c ^ (r & 7)) << 4);
            const size_t go = (size_t)(kv0 + r) * HDIM + h * DKH + c * 8;
            cp16(kb + off,        Kh + go);
            cp16(kb + 8192 + off, Vh + go);
        }
        cp_commit();
    };

    issue_tile(0, 0);   // group0 also contains Q
    issue_tile(1, 1);

    float o[8][4];
#pragma unroll
    for (int j = 0; j < 8; j++)
#pragma unroll
        for (int e = 0; e < 4; e++) o[j][e] = 0.0f;
    float m0 = -INFINITY, m1 = -INFINITY;
    float l0 = 0.0f, l1 = 0.0f;

#pragma unroll 1
    for (int ti = 0; ti < ntiles; ti++) {
        if (ti < ntiles - 1) cp_wait<1>(); else cp_wait<0>();
        __syncthreads();
        if (ti + 2 < ntiles) issue_tile(ti + 2, (ti + 2) % 3);

        const uint32_t kb = sbase + 16384 + (ti % 3) * 16384;
        const uint32_t vb = kb + 8192;

        // S = Q @ K^T  (Q pre-scaled 1/8)
        float s[8][4];
#pragma unroll
        for (int j = 0; j < 8; j++)
#pragma unroll
            for (int e = 0; e < 4; e++) s[j][e] = 0.0f;

#pragma unroll
        for (int kk = 0; kk < 64; kk += 16) {
            uint32_t a[4];
            {
                const int row = wm + (lane & 15);
                const int ch  = (kk >> 3) + (lane >> 4);
                ldsm_x4(a[0], a[1], a[2], a[3],
                        sbase + row * 128 + ((ch ^ (row & 7)) << 4));
            }
#pragma unroll
            for (int j0 = 0; j0 < 8; j0 += 2) {
                uint32_t r0, r1, r2, r3;
                const int row = j0 * 8 + (lane & 15);
                const int ch  = (kk >> 3) + (lane >> 4);
                ldsm_x4(r0, r1, r2, r3, kb + row * 128 + ((ch ^ (row & 7)) << 4));
                uint32_t b0[2] = {r0, r2};
                uint32_t b1[2] = {r1, r3};
                mma_f16(s[j0],     a, b0);
                mma_f16(s[j0 + 1], a, b1);
            }
        }

        // online softmax (rows wm+g, wm+g+8)
        float mx0 = -INFINITY, mx1 = -INFINITY;
#pragma unroll
        for (int j = 0; j < 8; j++) {
            mx0 = fmaxf(mx0, fmaxf(s[j][0], s[j][1]));
            mx1 = fmaxf(mx1, fmaxf(s[j][2], s[j][3]));
        }
        mx0 = fmaxf(mx0, __shfl_xor_sync(0xffffffffu, mx0, 1));
        mx0 = fmaxf(mx0, __shfl_xor_sync(0xffffffffu, mx0, 2));
        mx1 = fmaxf(mx1, __shfl_xor_sync(0xffffffffu, mx1, 1));
        mx1 = fmaxf(mx1, __shfl_xor_sync(0xffffffffu, mx1, 2));

        const float mn0 = fmaxf(m0, mx0);
        const float mn1 = fmaxf(m1, mx1);
        const float f0  = __expf(m0 - mn0);
        const float f1  = __expf(m1 - mn1);

        float ls0 = 0.0f, ls1 = 0.0f;
#pragma unroll
        for (int j = 0; j < 8; j++) {
            s[j][0] = __expf(s[j][0] - mn0);
            s[j][1] = __expf(s[j][1] - mn0);
            s[j][2] = __expf(s[j][2] - mn1);
            s[j][3] = __expf(s[j][3] - mn1);
            ls0 += s[j][0] + s[j][1];
            ls1 += s[j][2] + s[j][3];
        }
        ls0 += __shfl_xor_sync(0xffffffffu, ls0, 1);
        ls0 += __shfl_xor_sync(0xffffffffu, ls0, 2);
        ls1 += __shfl_xor_sync(0xffffffffu, ls1, 1);
        ls1 += __shfl_xor_sync(0xffffffffu, ls1, 2);

        l0 = l0 * f0 + ls0;
        l1 = l1 * f1 + ls1;
        m0 = mn0;  m1 = mn1;

#pragma unroll
        for (int j = 0; j < 8; j++) {
            o[j][0] *= f0; o[j][1] *= f0;
            o[j][2] *= f1; o[j][3] *= f1;
        }

        // O += P @ V  (P from registers)
#pragma unroll
        for (int kk = 0; kk < 64; kk += 16) {
            const int j0 = kk >> 3;
            uint32_t a[4];
            a[0] = pack2(s[j0][0],     s[j0][1]);
            a[1] = pack2(s[j0][2],     s[j0][3]);
            a[2] = pack2(s[j0 + 1][0], s[j0 + 1][1]);
            a[3] = pack2(s[j0 + 1][2], s[j0 + 1][3]);
#pragma unroll
            for (int jd = 0; jd < 8; jd += 2) {
                uint32_t b0[2], b1[2];
                const int row = kk + ((lane & 7) | (lane & 8));
                const int ch  = jd + (lane >> 4);
                ldsm_x4_t(b0[0], b0[1], b1[0], b1[1],
                          vb + row * 128 + ((ch ^ (row & 7)) << 4));
                mma_f16(o[jd],     a, b0);
                mma_f16(o[jd + 1], a, b1);
            }
        }
    }

    const float inv0 = 1.0f / l0;
    const float inv1 = 1.0f / l1;
    const int row0 = q0 + wm + g;
#pragma unroll
    for (int jd = 0; jd < 8; jd++) {
        const int col = h * DKH + jd * 8 + 2 * t;
        Oh[row0 * (HDIM / 2) + (col >> 1)]       = pack2(o[jd][0] * inv0, o[jd][1] * inv0);
        Oh[(row0 + 8) * (HDIM / 2) + (col >> 1)] = pack2(o[jd][2] * inv1, o[jd][3] * inv1);
    }
}

// ---------------------------------------------------------------------------
extern "C" void kernel_launch(void* const* d_in, const int* in_sizes, int n_in,
                              void* d_out, int out_size) {
    const float* x  = (const float*)d_in[0];
    const float* Wq = (const float*)d_in[1];
    const float* bq = (const float*)d_in[2];
    const float* Wk = (const float*)d_in[3];
    const float* bk = (const float*)d_in[4];
    const float* Wv = (const float*)d_in[5];
    const float* bv = (const float*)d_in[6];
    const float* Wo = (const float*)d_in[7];
    const float* bo = (const float*)d_in[8];
    float* out = (float*)d_out;

    float *q, *k;
    uint32_t *xh, *wqh, *wkh, *wvh, *woh, *qh, *kh, *vh, *ah;
    cudaGetSymbolAddress((void**)&q,   g_q);
    cudaGetSymbolAddress((void**)&k,   g_k);
    cudaGetSymbolAddress((void**)&xh,  g_xh);
    cudaGetSymbolAddress((void**)&wqh, g_wqh);
    cudaGetSymbolAddress((void**)&wkh, g_wkh);
    cudaGetSymbolAddress((void**)&wvh, g_wvh);
    cudaGetSymbolAddress((void**)&woh, g_woh);
    cudaGetSymbolAddress((void**)&qh,  g_qh);
    cudaGetSymbolAddress((void**)&kh,  g_kh);
    cudaGetSymbolAddress((void**)&vh,  g_vh);
    cudaGetSymbolAddress((void**)&ah,  g_ah);

    // one-time fp32 -> fp16 conversions
    const int xw4 = TSEQ * DEMB / 4;
    const int ww4 = DEMB * HDIM / 4;
    cvt_f16_kernel<<<(xw4 + 255) / 256, 256>>>((const float4*)x,  (uint2*)xh,  xw4);
    cvt_f16_kernel<<<(ww4 + 255) / 256, 256>>>((const float4*)Wq, (uint2*)wqh, ww4);
    cvt_f16_kernel<<<(ww4 + 255) / 256, 256>>>((const float4*)Wk, (uint2*)wkh, ww4);
    cvt_f16_kernel<<<(ww4 + 255) / 256, 256>>>((const float4*)Wv, (uint2*)wvh, ww4);
    cvt_f16_kernel<<<(ww4 + 255) / 256, 256>>>((const float4*)Wo, (uint2*)woh, ww4);

    const int gemm_smem  = 3 * 32768;   // 96 KB
    const int flash_smem = 4 * 16384;   // 64 KB
    cudaFuncSetAttribute(gemm_f16_kernel<false>,
                         cudaFuncAttributeMaxDynamicSharedMemorySize, gemm_smem);
    cudaFuncSetAttribute(gemm_f16_kernel<true>,
                         cudaFuncAttributeMaxDynamicSharedMemorySize, gemm_smem);
    cudaFuncSetAttribute(flash_f16_kernel,
                         cudaFuncAttributeMaxDynamicSharedMemorySize, flash_smem);

    dim3 blk(256);
    dim3 grd(HDIM / 128, TSEQ / 128);   // (8, 32)

    gemm_f16_kernel<false><<<grd, blk, gemm_smem>>>((const __half*)xh, (const __half*)wqh, bq, q,  TSEQ, HDIM, DEMB);
    gemm_f16_kernel<false><<<grd, blk, gemm_smem>>>((const __half*)xh, (const __half*)wkh, bk, k,  TSEQ, HDIM, DEMB);
    gemm_f16_kernel<true ><<<grd, blk, gemm_smem>>>((const __half*)xh, (const __half*)wvh, bv, vh, TSEQ, HDIM, DEMB);

    rotary_pack_kernel<<<TSEQ, 256>>>(q, k, qh, kh);

    flash_f16_kernel<<<dim3(TSEQ / 128, NHEADS), 256, flash_smem>>>(
        (const __half*)qh, (const __half*)kh, (const __half*)vh, ah);

    gemm_f16_kernel<false><<<grd, blk, gemm_smem>>>((const __half*)ah, (const __half*)woh, bo, out, TSEQ, HDIM, HDIM);
}

// round 6
// speedup vs baseline: 31.3825x; 1.0559x over previous
#include <cuda_runtime.h>
#include <cuda_fp16.h>
#include <math.h>
#include <stdint.h>

#define TSEQ   4096
#define DEMB   1024
#define NHEADS 16
#define DKH    64
#define HDIM   1024

// Scratch (allocation-free rule: __device__ globals)
__device__ uint32_t g_xh[TSEQ * DEMB / 2];     // x fp16
__device__ uint32_t g_wqh[DEMB * HDIM / 2];    // weights fp16
__device__ uint32_t g_wkh[DEMB * HDIM / 2];
__device__ uint32_t g_wvh[DEMB * HDIM / 2];
__device__ uint32_t g_woh[HDIM * HDIM / 2];
__device__ uint32_t g_qh[TSEQ * HDIM / 2];     // rotary Q fp16 (pre-scaled 0.125)
__device__ uint32_t g_kh[TSEQ * HDIM / 2];     // rotary K fp16
__device__ uint32_t g_vh[TSEQ * HDIM / 2];     // V fp16
__device__ uint32_t g_ah[TSEQ * HDIM / 2];     // attn out fp16

#define ROPE_C 0.4152410118609203f   // log2(10000)/32

__device__ __forceinline__ uint32_t pack2(float lo, float hi) {
    __half2 h = __floats2half2_rn(lo, hi);
    return *(uint32_t*)&h;
}

__device__ __forceinline__ void mma_f16(float c[4], const uint32_t a[4], const uint32_t b[2]) {
    asm volatile(
        "mma.sync.aligned.m16n8k16.row.col.f32.f16.f16.f32 "
        "{%0,%1,%2,%3},{%4,%5,%6,%7},{%8,%9},{%0,%1,%2,%3};\n"
        : "+f"(c[0]), "+f"(c[1]), "+f"(c[2]), "+f"(c[3])
        : "r"(a[0]), "r"(a[1]), "r"(a[2]), "r"(a[3]), "r"(b[0]), "r"(b[1]));
}

__device__ __forceinline__ void ldsm_x4(uint32_t& r0, uint32_t& r1, uint32_t& r2, uint32_t& r3,
                                        uint32_t addr) {
    asm volatile("ldmatrix.sync.aligned.m8n8.x4.shared.b16 {%0,%1,%2,%3}, [%4];"
                 : "=r"(r0), "=r"(r1), "=r"(r2), "=r"(r3) : "r"(addr));
}

__device__ __forceinline__ void ldsm_x4_t(uint32_t& r0, uint32_t& r1, uint32_t& r2, uint32_t& r3,
                                          uint32_t addr) {
    asm volatile("ldmatrix.sync.aligned.m8n8.x4.trans.shared.b16 {%0,%1,%2,%3}, [%4];"
                 : "=r"(r0), "=r"(r1), "=r"(r2), "=r"(r3) : "r"(addr));
}

__device__ __forceinline__ void cp16(uint32_t smem, const void* gmem) {
    asm volatile("cp.async.cg.shared.global [%0], [%1], 16;\n" :: "r"(smem), "l"(gmem));
}
__device__ __forceinline__ void cp_commit() {
    asm volatile("cp.async.commit_group;\n");
}
template <int N> __device__ __forceinline__ void cp_wait() {
    asm volatile("cp.async.wait_group %0;\n" :: "n"(N));
}

// ---------------------------------------------------------------------------
// One-shot fp32 -> fp16 conversion of x + 4 weight matrices.
// ---------------------------------------------------------------------------
#define XW4 (TSEQ * DEMB / 4)
#define WW4 (DEMB * HDIM / 4)

__global__ void cvt_all_kernel(const float4* __restrict__ x,
                               const float4* __restrict__ wq, const float4* __restrict__ wk,
                               const float4* __restrict__ wv, const float4* __restrict__ wo,
                               uint2* __restrict__ xh,
                               uint2* __restrict__ wqh, uint2* __restrict__ wkh,
                               uint2* __restrict__ wvh, uint2* __restrict__ woh) {
    const int i = blockIdx.x * blockDim.x + threadIdx.x;
    const float4* src;
    uint2* dst;
    int off;
    if (i < XW4)                { src = x;  dst = xh;  off = i; }
    else {
        const int j = i - XW4;
        const int seg = j / WW4;
        off = j - seg * WW4;
        switch (seg) {
            case 0:  src = wq; dst = wqh; break;
            case 1:  src = wk; dst = wkh; break;
            case 2:  src = wv; dst = wvh; break;
            default: src = wo; dst = woh; break;
        }
    }
    float4 v = src[off];
    uint2 u;
    u.x = pack2(v.x, v.y);
    u.y = pack2(v.z, v.w);
    dst[off] = u;
}

// ---------------------------------------------------------------------------
// Fused QKV GEMM (+RoPE for Q/K): blockIdx.z selects {Q,K,V}.
// Block 128x128, 8 warps, BK=64, 3-stage cp.async ring, SW128 swizzle.
// Z=0: rope(acc)*0.125 -> g_qh ; Z=1: rope(acc) -> g_kh ; Z=2: acc -> g_vh.
// Rope epilogue stages the fp32 tile in smem (reusing the ring buffers).
// ---------------------------------------------------------------------------
#define ST_S 130   // epilogue staging row stride (floats)

__global__ __launch_bounds__(256, 2) void qkv_gemm_kernel(
    const __half* __restrict__ A,
    const __half* __restrict__ Bq, const __half* __restrict__ Bk, const __half* __restrict__ Bv,
    const float* __restrict__ bq, const float* __restrict__ bk, const float* __restrict__ bv,
    uint32_t* __restrict__ Oq, uint32_t* __restrict__ Ok, uint32_t* __restrict__ Ov)
{
    extern __shared__ char smem[];
    const uint32_t sbase = (uint32_t)__cvta_generic_to_shared(smem);

    const int z = blockIdx.z;
    const __half* B    = (z == 0) ? Bq : (z == 1) ? Bk : Bv;
    const float*  bias = (z == 0) ? bq : (z == 1) ? bk : bv;
    uint32_t*     Oh   = (z == 0) ? Oq : (z == 1) ? Ok : Ov;

    const int tid  = threadIdx.x;
    const int lane = tid & 31;
    const int wid  = tid >> 5;
    const int g    = lane >> 2;
    const int t    = lane & 3;
    const int wm   = (wid >> 2) * 64;
    const int wn   = (wid & 3) * 32;
    const int gm   = blockIdx.y * 128;
    const int gn   = blockIdx.x * 128;
    const int K    = DEMB;
    const int nk   = K >> 6;

    float acc[4][4][4];
#pragma unroll
    for (int i = 0; i < 4; i++)
#pragma unroll
        for (int j = 0; j < 4; j++)
#pragma unroll
            for (int e = 0; e < 4; e++) acc[i][j][e] = 0.0f;

    auto issue = [&](int kc, int st) {
        const uint32_t sa = sbase + st * 32768;
#pragma unroll
        for (int i = 0; i < 4; i++) {
            const int idx = tid + 256 * i;
            const int r = idx >> 3, c = idx & 7;
            cp16(sa + r * 128 + ((c ^ (r & 7)) << 4),
                 A + (size_t)(gm + r) * K + kc * 64 + c * 8);
        }
#pragma unroll
        for (int i = 0; i < 4; i++) {
            const int idx = tid + 256 * i;
            const int r = idx >> 4, c = idx & 15;
            cp16(sa + 16384 + r * 256 + ((c ^ (r & 7)) << 4),
                 B + (size_t)(kc * 64 + r) * HDIM + gn + c * 8);
        }
        cp_commit();
    };

    issue(0, 0);
    issue(1, 1);

#pragma unroll 1
    for (int kc = 0; kc < nk; kc++) {
        if (kc < nk - 1) cp_wait<1>(); else cp_wait<0>();
        __syncthreads();
        if (kc + 2 < nk) issue(kc + 2, (kc + 2) % 3);

        const uint32_t sa = sbase + (kc % 3) * 32768;
#pragma unroll
        for (int kk = 0; kk < 64; kk += 16) {
            uint32_t af[4][4], bf[4][2];
#pragma unroll
            for (int i = 0; i < 4; i++) {
                const int row = wm + i * 16 + (lane & 15);
                const int ch  = (kk >> 3) + (lane >> 4);
                ldsm_x4(af[i][0], af[i][1], af[i][2], af[i][3],
                        sa + row * 128 + ((ch ^ (row & 7)) << 4));
            }
#pragma unroll
            for (int nb = 0; nb < 2; nb++) {
                const int row = kk + ((lane & 7) | (lane & 8));
                const int ch  = ((wn + nb * 16) >> 3) + ((lane >> 4) & 1);
                ldsm_x4_t(bf[2 * nb][0], bf[2 * nb][1], bf[2 * nb + 1][0], bf[2 * nb + 1][1],
                          sa + 16384 + row * 256 + ((ch ^ (row & 7)) << 4));
            }
#pragma unroll
            for (int i = 0; i < 4; i++)
#pragma unroll
                for (int j = 0; j < 4; j++)
                    mma_f16(acc[i][j], af[i], bf[j]);
        }
    }

    if (z == 2) {
        // V: plain fp16 output
#pragma unroll
        for (int i = 0; i < 4; i++) {
            const int row0 = gm + wm + i * 16 + g;
#pragma unroll
            for (int j = 0; j < 4; j++) {
                const int col = gn + wn + j * 8 + 2 * t;
                const float2 bv2 = *(const float2*)&bias[col];
                Oh[(row0 * HDIM + col) >> 1]       = pack2(acc[i][j][0] + bv2.x, acc[i][j][1] + bv2.y);
                Oh[((row0 + 8) * HDIM + col) >> 1] = pack2(acc[i][j][2] + bv2.x, acc[i][j][3] + bv2.y);
            }
        }
        return;
    }

    // Q/K: stage fp32 tile in smem, apply RoPE, write fp16
    __syncthreads();           // all warps done with ring buffers
    float* st = (float*)smem;  // [128][ST_S]
#pragma unroll
    for (int i = 0; i < 4; i++) {
        const int r0 = wm + i * 16 + g;
#pragma unroll
        for (int j = 0; j < 4; j++) {
            const int col = wn + j * 8 + 2 * t;
            const float2 bv2 = *(const float2*)&bias[gn + col];
            float2 v0, v1;
            v0.x = acc[i][j][0] + bv2.x;  v0.y = acc[i][j][1] + bv2.y;
            v1.x = acc[i][j][2] + bv2.x;  v1.y = acc[i][j][3] + bv2.y;
            *(float2*)&st[r0 * ST_S + col]       = v0;
            *(float2*)&st[(r0 + 8) * ST_S + col] = v1;
        }
    }
    __syncthreads();

    const float sc = (z == 0) ? 0.125f : 1.0f;
#pragma unroll 1
    for (int it = 0; it < 16; it++) {
        const int idx = it * 256 + tid;     // 0..4095
        const int row = idx >> 5;           // 0..127
        const int pp  = idx & 31;           // pair-pair within 128 cols
        const int hs  = pp >> 4;            // head select (0/1)
        const int pi  = pp & 15;            // covers dims 2pi, 2pi+1 (+32 partners)
        const int c0  = hs * 64 + 2 * pi;
        const int pos = gm + row;

        float s0, cc0, s1, cc1;
        sincosf((float)pos * exp2f(-(float)(2 * pi)     * ROPE_C), &s0, &cc0);
        sincosf((float)pos * exp2f(-(float)(2 * pi + 1) * ROPE_C), &s1, &cc1);

        const float2 x1 = *(const float2*)&st[row * ST_S + c0];
        const float2 x2 = *(const float2*)&st[row * ST_S + c0 + 32];

        const uint32_t o1 = pack2((x1.x * cc0 - x2.x * s0) * sc, (x1.y * cc1 - x2.y * s1) * sc);
        const uint32_t o2 = pack2((x2.x * cc0 + x1.x * s0) * sc, (x2.y * cc1 + x1.y * s1) * sc);

        const int ui = pos * (HDIM / 2) + ((gn + c0) >> 1);
        Oh[ui]      = o1;
        Oh[ui + 16] = o2;
    }
}

// ---------------------------------------------------------------------------
// Out-projection GEMM: fp16 A,B -> fp32 out (+bias). Same structure.
// ---------------------------------------------------------------------------
__global__ __launch_bounds__(256, 2) void gemm_f16_f32_kernel(
    const __half* __restrict__ A, const __half* __restrict__ B,
    const float* __restrict__ bias, float* __restrict__ C,
    int M, int N, int K)
{
    extern __shared__ char smem[];
    const uint32_t sbase = (uint32_t)__cvta_generic_to_shared(smem);

    const int tid  = threadIdx.x;
    const int lane = tid & 31;
    const int wid  = tid >> 5;
    const int g    = lane >> 2;
    const int t    = lane & 3;
    const int wm   = (wid >> 2) * 64;
    const int wn   = (wid & 3) * 32;
    const int gm   = blockIdx.y * 128;
    const int gn   = blockIdx.x * 128;
    const int nk   = K >> 6;

    float acc[4][4][4];
#pragma unroll
    for (int i = 0; i < 4; i++)
#pragma unroll
        for (int j = 0; j < 4; j++)
#pragma unroll
            for (int e = 0; e < 4; e++) acc[i][j][e] = 0.0f;

    auto issue = [&](int kc, int st) {
        const uint32_t sa = sbase + st * 32768;
#pragma unroll
        for (int i = 0; i < 4; i++) {
            const int idx = tid + 256 * i;
            const int r = idx >> 3, c = idx & 7;
            cp16(sa + r * 128 + ((c ^ (r & 7)) << 4),
                 A + (size_t)(gm + r) * K + kc * 64 + c * 8);
        }
#pragma unroll
        for (int i = 0; i < 4; i++) {
            const int idx = tid + 256 * i;
            const int r = idx >> 4, c = idx & 15;
            cp16(sa + 16384 + r * 256 + ((c ^ (r & 7)) << 4),
                 B + (size_t)(kc * 64 + r) * N + gn + c * 8);
        }
        cp_commit();
    };

    issue(0, 0);
    issue(1, 1);

#pragma unroll 1
    for (int kc = 0; kc < nk; kc++) {
        if (kc < nk - 1) cp_wait<1>(); else cp_wait<0>();
        __syncthreads();
        if (kc + 2 < nk) issue(kc + 2, (kc + 2) % 3);

        const uint32_t sa = sbase + (kc % 3) * 32768;
#pragma unroll
        for (int kk = 0; kk < 64; kk += 16) {
            uint32_t af[4][4], bf[4][2];
#pragma unroll
            for (int i = 0; i < 4; i++) {
                const int row = wm + i * 16 + (lane & 15);
                const int ch  = (kk >> 3) + (lane >> 4);
                ldsm_x4(af[i][0], af[i][1], af[i][2], af[i][3],
                        sa + row * 128 + ((ch ^ (row & 7)) << 4));
            }
#pragma unroll
            for (int nb = 0; nb < 2; nb++) {
                const int row = kk + ((lane & 7) | (lane & 8));
                const int ch  = ((wn + nb * 16) >> 3) + ((lane >> 4) & 1);
                ldsm_x4_t(bf[2 * nb][0], bf[2 * nb][1], bf[2 * nb + 1][0], bf[2 * nb + 1][1],
                          sa + 16384 + row * 256 + ((ch ^ (row & 7)) << 4));
            }
#pragma unroll
            for (int i = 0; i < 4; i++)
#pragma unroll
                for (int j = 0; j < 4; j++)
                    mma_f16(acc[i][j], af[i], bf[j]);
        }
    }

#pragma unroll
    for (int i = 0; i < 4; i++) {
        const int row0 = gm + wm + i * 16 + g;
#pragma unroll
        for (int j = 0; j < 4; j++) {
            const int col = gn + wn + j * 8 + 2 * t;
            const float2 bv = *(const float2*)&bias[col];
            float2 o0, o1;
            o0.x = acc[i][j][0] + bv.x;  o0.y = acc[i][j][1] + bv.y;
            o1.x = acc[i][j][2] + bv.x;  o1.y = acc[i][j][3] + bv.y;
            *(float2*)&C[row0 * N + col]       = o0;
            *(float2*)&C[(row0 + 8) * N + col] = o1;
        }
    }
}

// ---------------------------------------------------------------------------
// Flash attention fp16. Block = (128 q rows, head), 8 warps; K/V 3-stage
// cp.async ring; P in registers. 64KB smem.
// ---------------------------------------------------------------------------
__global__ __launch_bounds__(256) void flash_f16_kernel(
    const __half* __restrict__ Qh, const __half* __restrict__ Kh,
    const __half* __restrict__ Vh, uint32_t* __restrict__ Oh)
{
    extern __shared__ char smem[];
    const uint32_t sbase = (uint32_t)__cvta_generic_to_shared(smem);

    const int h    = blockIdx.y;
    const int q0   = blockIdx.x * 128;
    const int tid  = threadIdx.x;
    const int lane = tid & 31;
    const int wid  = tid >> 5;
    const int g    = lane >> 2;
    const int t    = lane & 3;
    const int wm   = wid * 16;
    const int ntiles = TSEQ / 64;

    // prologue: Q into group0
#pragma unroll
    for (int i = 0; i < 4; i++) {
        const int idx = tid + 256 * i;
        const int r = idx >> 3, c = idx & 7;
        cp16(sbase + r * 128 + ((c ^ (r & 7)) << 4),
             Qh + (size_t)(q0 + r) * HDIM + h * DKH + c * 8);
    }

    auto issue_tile = [&](int tile, int st) {
        const uint32_t kb = sbase + 16384 + st * 16384;
        const int kv0 = tile * 64;
#pragma unroll
        for (int i = 0; i < 2; i++) {
            const int idx = tid + 256 * i;
            const int r = idx >> 3, c = idx & 7;
            const uint32_t off = r * 128 + ((c ^ (r & 7)) << 4);
            const size_t go = (size_t)(kv0 + r) * HDIM + h * DKH + c * 8;
            cp16(kb + off,        Kh + go);
            cp16(kb + 8192 + off, Vh + go);
        }
        cp_commit();
    };

    issue_tile(0, 0);
    issue_tile(1, 1);

    float o[8][4];
#pragma unroll
    for (int j = 0; j < 8; j++)
#pragma unroll
        for (int e = 0; e < 4; e++) o[j][e] = 0.0f;
    float m0 = -INFINITY, m1 = -INFINITY;
    float l0 = 0.0f, l1 = 0.0f;

#pragma unroll 1
    for (int ti = 0; ti < ntiles; ti++) {
        if (ti < ntiles - 1) cp_wait<1>(); else cp_wait<0>();
        __syncthreads();
        if (ti + 2 < ntiles) issue_tile(ti + 2, (ti + 2) % 3);

        const uint32_t kb = sbase + 16384 + (ti % 3) * 16384;
        const uint32_t vb = kb + 8192;

        float s[8][4];
#pragma unroll
        for (int j = 0; j < 8; j++)
#pragma unroll
            for (int e = 0; e < 4; e++) s[j][e] = 0.0f;

#pragma unroll
        for (int kk = 0; kk < 64; kk += 16) {
            uint32_t a[4];
            {
                const int row = wm + (lane & 15);
                const int ch  = (kk >> 3) + (lane >> 4);
                ldsm_x4(a[0], a[1], a[2], a[3],
                        sbase + row * 128 + ((ch ^ (row & 7)) << 4));
            }
#pragma unroll
            for (int j0 = 0; j0 < 8; j0 += 2) {
                uint32_t r0, r1, r2, r3;
                const int row = j0 * 8 + (lane & 15);
                const int ch  = (kk >> 3) + (lane >> 4);
                ldsm_x4(r0, r1, r2, r3, kb + row * 128 + ((ch ^ (row & 7)) << 4));
                uint32_t b0[2] = {r0, r2};
                uint32_t b1[2] = {r1, r3};
                mma_f16(s[j0],     a, b0);
                mma_f16(s[j0 + 1], a, b1);
            }
        }

        float mx0 = -INFINITY, mx1 = -INFINITY;
#pragma unroll
        for (int j = 0; j < 8; j++) {
            mx0 = fmaxf(mx0, fmaxf(s[j][0], s[j][1]));
            mx1 = fmaxf(mx1, fmaxf(s[j][2], s[j][3]));
        }
        mx0 = fmaxf(mx0, __shfl_xor_sync(0xffffffffu, mx0, 1));
        mx0 = fmaxf(mx0, __shfl_xor_sync(0xffffffffu, mx0, 2));
        mx1 = fmaxf(mx1, __shfl_xor_sync(0xffffffffu, mx1, 1));
        mx1 = fmaxf(mx1, __shfl_xor_sync(0xffffffffu, mx1, 2));

        const float mn0 = fmaxf(m0, mx0);
        const float mn1 = fmaxf(m1, mx1);
        const float f0  = __expf(m0 - mn0);
        const float f1  = __expf(m1 - mn1);

        float ls0 = 0.0f, ls1 = 0.0f;
#pragma unroll
        for (int j = 0; j < 8; j++) {
            s[j][0] = __expf(s[j][0] - mn0);
            s[j][1] = __expf(s[j][1] - mn0);
            s[j][2] = __expf(s[j][2] - mn1);
            s[j][3] = __expf(s[j][3] - mn1);
            ls0 += s[j][0] + s[j][1];
            ls1 += s[j][2] + s[j][3];
        }
        ls0 += __shfl_xor_sync(0xffffffffu, ls0, 1);
        ls0 += __shfl_xor_sync(0xffffffffu, ls0, 2);
        ls1 += __shfl_xor_sync(0xffffffffu, ls1, 1);
        ls1 += __shfl_xor_sync(0xffffffffu, ls1, 2);

        l0 = l0 * f0 + ls0;
        l1 = l1 * f1 + ls1;
        m0 = mn0;  m1 = mn1;

#pragma unroll
        for (int j = 0; j < 8; j++) {
            o[j][0] *= f0; o[j][1] *= f0;
            o[j][2] *= f1; o[j][3] *= f1;
        }

#pragma unroll
        for (int kk = 0; kk < 64; kk += 16) {
            const int j0 = kk >> 3;
            uint32_t a[4];
            a[0] = pack2(s[j0][0],     s[j0][1]);
            a[1] = pack2(s[j0][2],     s[j0][3]);
            a[2] = pack2(s[j0 + 1][0], s[j0 + 1][1]);
            a[3] = pack2(s[j0 + 1][2], s[j0 + 1][3]);
#pragma unroll
            for (int jd = 0; jd < 8; jd += 2) {
                uint32_t b0[2], b1[2];
                const int row = kk + ((lane & 7) | (lane & 8));
                const int ch  = jd + (lane >> 4);
                ldsm_x4_t(b0[0], b0[1], b1[0], b1[1],
                          vb + row * 128 + ((ch ^ (row & 7)) << 4));
                mma_f16(o[jd],     a, b0);
                mma_f16(o[jd + 1], a, b1);
            }
        }
    }

    const float inv0 = 1.0f / l0;
    const float inv1 = 1.0f / l1;
    const int row0 = q0 + wm + g;
#pragma unroll
    for (int jd = 0; jd < 8; jd++) {
        const int col = h * DKH + jd * 8 + 2 * t;
        Oh[row0 * (HDIM / 2) + (col >> 1)]       = pack2(o[jd][0] * inv0, o[jd][1] * inv0);
        Oh[(row0 + 8) * (HDIM / 2) + (col >> 1)] = pack2(o[jd][2] * inv1, o[jd][3] * inv1);
    }
}

// ---------------------------------------------------------------------------
extern "C" void kernel_launch(void* const* d_in, const int* in_sizes, int n_in,
                              void* d_out, int out_size) {
    const float* x  = (const float*)d_in[0];
    const float* Wq = (const float*)d_in[1];
    const float* bq = (const float*)d_in[2];
    const float* Wk = (const float*)d_in[3];
    const float* bk = (const float*)d_in[4];
    const float* Wv = (const float*)d_in[5];
    const float* bv = (const float*)d_in[6];
    const float* Wo = (const float*)d_in[7];
    const float* bo = (const float*)d_in[8];
    float* out = (float*)d_out;

    uint32_t *xh, *wqh, *wkh, *wvh, *woh, *qh, *kh, *vh, *ah;
    cudaGetSymbolAddress((void**)&xh,  g_xh);
    cudaGetSymbolAddress((void**)&wqh, g_wqh);
    cudaGetSymbolAddress((void**)&wkh, g_wkh);
    cudaGetSymbolAddress((void**)&wvh, g_wvh);
    cudaGetSymbolAddress((void**)&woh, g_woh);
    cudaGetSymbolAddress((void**)&qh,  g_qh);
    cudaGetSymbolAddress((void**)&kh,  g_kh);
    cudaGetSymbolAddress((void**)&vh,  g_vh);
    cudaGetSymbolAddress((void**)&ah,  g_ah);

    // one fused conversion launch
    const int total4 = XW4 + 4 * WW4;
    cvt_all_kernel<<<(total4 + 255) / 256, 256>>>(
        (const float4*)x, (const float4*)Wq, (const float4*)Wk,
        (const float4*)Wv, (const float4*)Wo,
        (uint2*)xh, (uint2*)wqh, (uint2*)wkh, (uint2*)wvh, (uint2*)woh);

    const int gemm_smem  = 3 * 32768;   // 96 KB
    const int flash_smem = 4 * 16384;   // 64 KB
    cudaFuncSetAttribute(qkv_gemm_kernel,
                         cudaFuncAttributeMaxDynamicSharedMemorySize, gemm_smem);
    cudaFuncSetAttribute(gemm_f16_f32_kernel,
                         cudaFuncAttributeMaxDynamicSharedMemorySize, gemm_smem);
    cudaFuncSetAttribute(flash_f16_kernel,
                         cudaFuncAttributeMaxDynamicSharedMemorySize, flash_smem);

    // fused QKV projections + RoPE
    qkv_gemm_kernel<<<dim3(HDIM / 128, TSEQ / 128, 3), 256, gemm_smem>>>(
        (const __half*)xh,
        (const __half*)wqh, (const __half*)wkh, (const __half*)wvh,
        bq, bk, bv, qh, kh, vh);

    // flash attention
    flash_f16_kernel<<<dim3(TSEQ / 128, NHEADS), 256, flash_smem>>>(
        (const __half*)qh, (const __half*)kh, (const __half*)vh, ah);

    // output projection
    gemm_f16_f32_kernel<<<dim3(HDIM / 128, TSEQ / 128), 256, gemm_smem>>>(
        (const __half*)ah, (const __half*)woh, bo, out, TSEQ, HDIM, HDIM);
}

// round 8
// speedup vs baseline: 32.3531x; 1.0309x over previous
#include <cuda_runtime.h>
#include <cuda_fp16.h>
#include <math.h>
#include <stdint.h>

#define TSEQ   4096
#define DEMB   1024
#define NHEADS 16
#define DKH    64
#define HDIM   1024

// Scratch (allocation-free rule: __device__ globals)
__device__ uint32_t g_xh[TSEQ * DEMB / 2];     // x fp16
__device__ uint32_t g_wqh[DEMB * HDIM / 2];    // weights fp16
__device__ uint32_t g_wkh[DEMB * HDIM / 2];
__device__ uint32_t g_wvh[DEMB * HDIM / 2];
__device__ uint32_t g_woh[HDIM * HDIM / 2];
__device__ uint32_t g_qh[TSEQ * HDIM / 2];     // rotary Q fp16 (pre-scaled 0.125)
__device__ uint32_t g_kh[TSEQ * HDIM / 2];     // rotary K fp16
__device__ uint32_t g_vh[TSEQ * HDIM / 2];     // V fp16
__device__ uint32_t g_ah[TSEQ * HDIM / 2];     // attn out fp16

#define ROPE_C 0.4152410118609203f   // log2(10000)/32

__device__ __forceinline__ uint32_t pack2(float lo, float hi) {
    __half2 h = __floats2half2_rn(lo, hi);
    return *(uint32_t*)&h;
}

__device__ __forceinline__ void mma_f16(float c[4], const uint32_t a[4], const uint32_t b[2]) {
    asm volatile(
        "mma.sync.aligned.m16n8k16.row.col.f32.f16.f16.f32 "
        "{%0,%1,%2,%3},{%4,%5,%6,%7},{%8,%9},{%0,%1,%2,%3};\n"
        : "+f"(c[0]), "+f"(c[1]), "+f"(c[2]), "+f"(c[3])
        : "r"(a[0]), "r"(a[1]), "r"(a[2]), "r"(a[3]), "r"(b[0]), "r"(b[1]));
}

__device__ __forceinline__ void ldsm_x4(uint32_t& r0, uint32_t& r1, uint32_t& r2, uint32_t& r3,
                                        uint32_t addr) {
    asm volatile("ldmatrix.sync.aligned.m8n8.x4.shared.b16 {%0,%1,%2,%3}, [%4];"
                 : "=r"(r0), "=r"(r1), "=r"(r2), "=r"(r3) : "r"(addr));
}

__device__ __forceinline__ void ldsm_x4_t(uint32_t& r0, uint32_t& r1, uint32_t& r2, uint32_t& r3,
                                          uint32_t addr) {
    asm volatile("ldmatrix.sync.aligned.m8n8.x4.trans.shared.b16 {%0,%1,%2,%3}, [%4];"
                 : "=r"(r0), "=r"(r1), "=r"(r2), "=r"(r3) : "r"(addr));
}

__device__ __forceinline__ void cp16(uint32_t smem, const void* gmem) {
    asm volatile("cp.async.cg.shared.global [%0], [%1], 16;\n" :: "r"(smem), "l"(gmem));
}
__device__ __forceinline__ void cp_commit() {
    asm volatile("cp.async.commit_group;\n");
}
template <int N> __device__ __forceinline__ void cp_wait() {
    asm volatile("cp.async.wait_group %0;\n" :: "n"(N));
}

// ---------------------------------------------------------------------------
// One-shot fp32 -> fp16 conversion of x + 4 weight matrices.
// ---------------------------------------------------------------------------
#define XW4 (TSEQ * DEMB / 4)
#define WW4 (DEMB * HDIM / 4)

__global__ void cvt_all_kernel(const float4* __restrict__ x,
                               const float4* __restrict__ wq, const float4* __restrict__ wk,
                               const float4* __restrict__ wv, const float4* __restrict__ wo,
                               uint2* __restrict__ xh,
                               uint2* __restrict__ wqh, uint2* __restrict__ wkh,
                               uint2* __restrict__ wvh, uint2* __restrict__ woh) {
    const int i = blockIdx.x * blockDim.x + threadIdx.x;
    const float4* src;
    uint2* dst;
    int off;
    if (i < XW4)                { src = x;  dst = xh;  off = i; }
    else {
        const int j = i - XW4;
        const int seg = j / WW4;
        off = j - seg * WW4;
        switch (seg) {
            case 0:  src = wq; dst = wqh; break;
            case 1:  src = wk; dst = wkh; break;
            case 2:  src = wv; dst = wvh; break;
            default: src = wo; dst = woh; break;
        }
    }
    float4 v = src[off];
    uint2 u;
    u.x = pack2(v.x, v.y);
    u.y = pack2(v.z, v.w);
    dst[off] = u;
}

// ---------------------------------------------------------------------------
// Fused QKV GEMM (+RoPE for Q/K): blockIdx.z selects {Q,K,V}.
// Block 128x128, 8 warps, BK=64, 3-stage cp.async ring, SW128 swizzle.
// ---------------------------------------------------------------------------
#define ST_S 130   // epilogue staging row stride (floats)

__global__ __launch_bounds__(256, 2) void qkv_gemm_kernel(
    const __half* __restrict__ A,
    const __half* __restrict__ Bq, const __half* __restrict__ Bk, const __half* __restrict__ Bv,
    const float* __restrict__ bq, const float* __restrict__ bk, const float* __restrict__ bv,
    uint32_t* __restrict__ Oq, uint32_t* __restrict__ Ok, uint32_t* __restrict__ Ov)
{
    extern __shared__ char smem[];
    const uint32_t sbase = (uint32_t)__cvta_generic_to_shared(smem);

    const int z = blockIdx.z;
    const __half* B    = (z == 0) ? Bq : (z == 1) ? Bk : Bv;
    const float*  bias = (z == 0) ? bq : (z == 1) ? bk : bv;
    uint32_t*     Oh   = (z == 0) ? Oq : (z == 1) ? Ok : Ov;

    const int tid  = threadIdx.x;
    const int lane = tid & 31;
    const int wid  = tid >> 5;
    const int g    = lane >> 2;
    const int t    = lane & 3;
    const int wm   = (wid >> 2) * 64;
    const int wn   = (wid & 3) * 32;
    const int gm   = blockIdx.y * 128;
    const int gn   = blockIdx.x * 128;
    const int K    = DEMB;
    const int nk   = K >> 6;

    float acc[4][4][4];
#pragma unroll
    for (int i = 0; i < 4; i++)
#pragma unroll
        for (int j = 0; j < 4; j++)
#pragma unroll
            for (int e = 0; e < 4; e++) acc[i][j][e] = 0.0f;

    auto issue = [&](int kc, int st) {
        const uint32_t sa = sbase + st * 32768;
#pragma unroll
        for (int i = 0; i < 4; i++) {
            const int idx = tid + 256 * i;
            const int r = idx >> 3, c = idx & 7;
            cp16(sa + r * 128 + ((c ^ (r & 7)) << 4),
                 A + (size_t)(gm + r) * K + kc * 64 + c * 8);
        }
#pragma unroll
        for (int i = 0; i < 4; i++) {
            const int idx = tid + 256 * i;
            const int r = idx >> 4, c = idx & 15;
            cp16(sa + 16384 + r * 256 + ((c ^ (r & 7)) << 4),
                 B + (size_t)(kc * 64 + r) * HDIM + gn + c * 8);
        }
        cp_commit();
    };

    issue(0, 0);
    issue(1, 1);

#pragma unroll 1
    for (int kc = 0; kc < nk; kc++) {
        if (kc < nk - 1) cp_wait<1>(); else cp_wait<0>();
        __syncthreads();
        if (kc + 2 < nk) issue(kc + 2, (kc + 2) % 3);

        const uint32_t sa = sbase + (kc % 3) * 32768;
#pragma unroll
        for (int kk = 0; kk < 64; kk += 16) {
            uint32_t af[4][4], bf[4][2];
#pragma unroll
            for (int i = 0; i < 4; i++) {
                const int row = wm + i * 16 + (lane & 15);
                const int ch  = (kk >> 3) + (lane >> 4);
                ldsm_x4(af[i][0], af[i][1], af[i][2], af[i][3],
                        sa + row * 128 + ((ch ^ (row & 7)) << 4));
            }
#pragma unroll
            for (int nb = 0; nb < 2; nb++) {
                const int row = kk + ((lane & 7) | (lane & 8));
                const int ch  = ((wn + nb * 16) >> 3) + ((lane >> 4) & 1);
                ldsm_x4_t(bf[2 * nb][0], bf[2 * nb][1], bf[2 * nb + 1][0], bf[2 * nb + 1][1],
                          sa + 16384 + row * 256 + ((ch ^ (row & 7)) << 4));
            }
#pragma unroll
            for (int i = 0; i < 4; i++)
#pragma unroll
                for (int j = 0; j < 4; j++)
                    mma_f16(acc[i][j], af[i], bf[j]);
        }
    }

    if (z == 2) {
#pragma unroll
        for (int i = 0; i < 4; i++) {
            const int row0 = gm + wm + i * 16 + g;
#pragma unroll
            for (int j = 0; j < 4; j++) {
                const int col = gn + wn + j * 8 + 2 * t;
                const float2 bv2 = *(const float2*)&bias[col];
                Oh[(row0 * HDIM + col) >> 1]       = pack2(acc[i][j][0] + bv2.x, acc[i][j][1] + bv2.y);
                Oh[((row0 + 8) * HDIM + col) >> 1] = pack2(acc[i][j][2] + bv2.x, acc[i][j][3] + bv2.y);
            }
        }
        return;
    }

    // Q/K: stage fp32 tile in smem, apply RoPE, write fp16
    __syncthreads();
    float* st = (float*)smem;  // [128][ST_S]
#pragma unroll
    for (int i = 0; i < 4; i++) {
        const int r0 = wm + i * 16 + g;
#pragma unroll
        for (int j = 0; j < 4; j++) {
            const int col = wn + j * 8 + 2 * t;
            const float2 bv2 = *(const float2*)&bias[gn + col];
            float2 v0, v1;
            v0.x = acc[i][j][0] + bv2.x;  v0.y = acc[i][j][1] + bv2.y;
            v1.x = acc[i][j][2] + bv2.x;  v1.y = acc[i][j][3] + bv2.y;
            *(float2*)&st[r0 * ST_S + col]       = v0;
            *(float2*)&st[(r0 + 8) * ST_S + col] = v1;
        }
    }
    __syncthreads();

    const float sc = (z == 0) ? 0.125f : 1.0f;
#pragma unroll 1
    for (int it = 0; it < 16; it++) {
        const int idx = it * 256 + tid;     // 0..4095
        const int row = idx >> 5;           // 0..127
        const int pp  = idx & 31;
        const int hs  = pp >> 4;
        const int pi  = pp & 15;
        const int c0  = hs * 64 + 2 * pi;
        const int pos = gm + row;

        float s0, cc0, s1, cc1;
        sincosf((float)pos * exp2f(-(float)(2 * pi)     * ROPE_C), &s0, &cc0);
        sincosf((float)pos * exp2f(-(float)(2 * pi + 1) * ROPE_C), &s1, &cc1);

        const float2 x1 = *(const float2*)&st[row * ST_S + c0];
        const float2 x2 = *(const float2*)&st[row * ST_S + c0 + 32];

        const uint32_t o1 = pack2((x1.x * cc0 - x2.x * s0) * sc, (x1.y * cc1 - x2.y * s1) * sc);
        const uint32_t o2 = pack2((x2.x * cc0 + x1.x * s0) * sc, (x2.y * cc1 + x1.y * s1) * sc);

        const int ui = pos * (HDIM / 2) + ((gn + c0) >> 1);
        Oh[ui]      = o1;
        Oh[ui + 16] = o2;
    }
}

// ---------------------------------------------------------------------------
// Out-projection GEMM: fp16 A,B -> fp32 out (+bias).
// ---------------------------------------------------------------------------
__global__ __launch_bounds__(256, 2) void gemm_f16_f32_kernel(
    const __half* __restrict__ A, const __half* __restrict__ B,
    const float* __restrict__ bias, float* __restrict__ C,
    int M, int N, int K)
{
    extern __shared__ char smem[];
    const uint32_t sbase = (uint32_t)__cvta_generic_to_shared(smem);

    const int tid  = threadIdx.x;
    const int lane = tid & 31;
    const int wid  = tid >> 5;
    const int g    = lane >> 2;
    const int t    = lane & 3;
    const int wm   = (wid >> 2) * 64;
    const int wn   = (wid & 3) * 32;
    const int gm   = blockIdx.y * 128;
    const int gn   = blockIdx.x * 128;
    const int nk   = K >> 6;

    float acc[4][4][4];
#pragma unroll
    for (int i = 0; i < 4; i++)
#pragma unroll
        for (int j = 0; j < 4; j++)
#pragma unroll
            for (int e = 0; e < 4; e++) acc[i][j][e] = 0.0f;

    auto issue = [&](int kc, int st) {
        const uint32_t sa = sbase + st * 32768;
#pragma unroll
        for (int i = 0; i < 4; i++) {
            const int idx = tid + 256 * i;
            const int r = idx >> 3, c = idx & 7;
            cp16(sa + r * 128 + ((c ^ (r & 7)) << 4),
                 A + (size_t)(gm + r) * K + kc * 64 + c * 8);
        }
#pragma unroll
        for (int i = 0; i < 4; i++) {
            const int idx = tid + 256 * i;
            const int r = idx >> 4, c = idx & 15;
            cp16(sa + 16384 + r * 256 + ((c ^ (r & 7)) << 4),
                 B + (size_t)(kc * 64 + r) * N + gn + c * 8);
        }
        cp_commit();
    };

    issue(0, 0);
    issue(1, 1);

#pragma unroll 1
    for (int kc = 0; kc < nk; kc++) {
        if (kc < nk - 1) cp_wait<1>(); else cp_wait<0>();
        __syncthreads();
        if (kc + 2 < nk) issue(kc + 2, (kc + 2) % 3);

        const uint32_t sa = sbase + (kc % 3) * 32768;
#pragma unroll
        for (int kk = 0; kk < 64; kk += 16) {
            uint32_t af[4][4], bf[4][2];
#pragma unroll
            for (int i = 0; i < 4; i++) {
                const int row = wm + i * 16 + (lane & 15);
                const int ch  = (kk >> 3) + (lane >> 4);
                ldsm_x4(af[i][0], af[i][1], af[i][2], af[i][3],
                        sa + row * 128 + ((ch ^ (row & 7)) << 4));
            }
#pragma unroll
            for (int nb = 0; nb < 2; nb++) {
                const int row = kk + ((lane & 7) | (lane & 8));
                const int ch  = ((wn + nb * 16) >> 3) + ((lane >> 4) & 1);
                ldsm_x4_t(bf[2 * nb][0], bf[2 * nb][1], bf[2 * nb + 1][0], bf[2 * nb + 1][1],
                          sa + 16384 + row * 256 + ((ch ^ (row & 7)) << 4));
            }
#pragma unroll
            for (int i = 0; i < 4; i++)
#pragma unroll
                for (int j = 0; j < 4; j++)
                    mma_f16(acc[i][j], af[i], bf[j]);
        }
    }

#pragma unroll
    for (int i = 0; i < 4; i++) {
        const int row0 = gm + wm + i * 16 + g;
#pragma unroll
        for (int j = 0; j < 4; j++) {
            const int col = gn + wn + j * 8 + 2 * t;
            const float2 bv = *(const float2*)&bias[col];
            float2 o0, o1;
            o0.x = acc[i][j][0] + bv.x;  o0.y = acc[i][j][1] + bv.y;
            o1.x = acc[i][j][2] + bv.x;  o1.y = acc[i][j][3] + bv.y;
            *(float2*)&C[row0 * N + col]       = o0;
            *(float2*)&C[(row0 + 8) * N + col] = o1;
        }
    }
}

// ---------------------------------------------------------------------------
// Flash attention fp16. Block = (128 q rows, head), 8 warps (16 rows each).
// KV tile = 128 keys per softmax round (s[16][4]); 2-stage cp.async ring,
// DEPTH-1 prefetch (stage (ti+1)&1 issued only after barrier — no clobber).
// Row-sum via ones-column MMA (shuffle-free, fp16-consistent with PV).
// Smem: 16KB Q + 2*32KB = 80KB.
// ---------------------------------------------------------------------------
__global__ __launch_bounds__(256, 2) void flash_f16_kernel(
    const __half* __restrict__ Qh, const __half* __restrict__ Kh,
    const __half* __restrict__ Vh, uint32_t* __restrict__ Oh)
{
    extern __shared__ char smem[];
    const uint32_t sbase = (uint32_t)__cvta_generic_to_shared(smem);

    const int h    = blockIdx.y;
    const int q0   = blockIdx.x * 128;
    const int tid  = threadIdx.x;
    const int lane = tid & 31;
    const int wid  = tid >> 5;
    const int g    = lane >> 2;
    const int t    = lane & 3;
    const int wm   = wid * 16;
    const int ntiles = TSEQ / 128;

    auto issue_tile = [&](int tile, int st) {
        const uint32_t kb = sbase + 16384 + st * 32768;
        const int kv0 = tile * 128;
#pragma unroll
        for (int i = 0; i < 4; i++) {
            const int idx = tid + 256 * i;        // 0..1023
            const int r = idx >> 3, c = idx & 7;  // r 0..127
            const uint32_t off = r * 128 + ((c ^ (r & 7)) << 4);
            const size_t go = (size_t)(kv0 + r) * HDIM + h * DKH + c * 8;
            cp16(kb + off,         Kh + go);
            cp16(kb + 16384 + off, Vh + go);
        }
        cp_commit();
    };

    // prologue: Q + tile0 (one group)
#pragma unroll
    for (int i = 0; i < 4; i++) {
        const int idx = tid + 256 * i;
        const int r = idx >> 3, c = idx & 7;
        cp16(sbase + r * 128 + ((c ^ (r & 7)) << 4),
             Qh + (size_t)(q0 + r) * HDIM + h * DKH + c * 8);
    }
    issue_tile(0, 0);

    float o[8][4];
#pragma unroll
    for (int j = 0; j < 8; j++)
#pragma unroll
        for (int e = 0; e < 4; e++) o[j][e] = 0.0f;
    float ls[4] = {0.0f, 0.0f, 0.0f, 0.0f};   // row-sum accumulator (ones-MMA)
    float m0 = -INFINITY, m1 = -INFINITY;
    const uint32_t bones[2] = {0x3C003C00u, 0x3C003C00u};   // half2(1,1)

#pragma unroll 1
    for (int ti = 0; ti < ntiles; ti++) {
        cp_wait<0>();          // tile ti (and, first iter, Q) resident
        __syncthreads();       // also separates prior reads of the other stage
        if (ti + 1 < ntiles) issue_tile(ti + 1, (ti + 1) & 1);   // depth-1 prefetch

        const uint32_t kb = sbase + 16384 + (ti & 1) * 32768;
        const uint32_t vb = kb + 16384;

        // S = Q @ K^T over 128 keys  (Q pre-scaled 1/8)
        float s[16][4];
#pragma unroll
        for (int j = 0; j < 16; j++)
#pragma unroll
            for (int e = 0; e < 4; e++) s[j][e] = 0.0f;

#pragma unroll
        for (int kk = 0; kk < 64; kk += 16) {
            uint32_t a[4];
            {
                const int row = wm + (lane & 15);
                const int ch  = (kk >> 3) + (lane >> 4);
                ldsm_x4(a[0], a[1], a[2], a[3],
                        sbase + row * 128 + ((ch ^ (row & 7)) << 4));
            }
#pragma unroll
            for (int j0 = 0; j0 < 16; j0 += 2) {
                uint32_t r0, r1, r2, r3;
                const int row = j0 * 8 + (lane & 15);
                const int ch  = (kk >> 3) + (lane >> 4);
                ldsm_x4(r0, r1, r2, r3, kb + row * 128 + ((ch ^ (row & 7)) << 4));
                uint32_t b0[2] = {r0, r2};
                uint32_t b1[2] = {r1, r3};
                mma_f16(s[j0],     a, b0);
                mma_f16(s[j0 + 1], a, b1);
            }
        }

        // online softmax (rows wm+g, wm+g+8) over 128 cols
        float mx0 = -INFINITY, mx1 = -INFINITY;
#pragma unroll
        for (int j = 0; j < 16; j++) {
            mx0 = fmaxf(mx0, fmaxf(s[j][0], s[j][1]));
            mx1 = fmaxf(mx1, fmaxf(s[j][2], s[j][3]));
        }
        mx0 = fmaxf(mx0, __shfl_xor_sync(0xffffffffu, mx0, 1));
        mx0 = fmaxf(mx0, __shfl_xor_sync(0xffffffffu, mx0, 2));
        mx1 = fmaxf(mx1, __shfl_xor_sync(0xffffffffu, mx1, 1));
        mx1 = fmaxf(mx1, __shfl_xor_sync(0xffffffffu, mx1, 2));

        const float mn0 = fmaxf(m0, mx0);
        const float mn1 = fmaxf(m1, mx1);
        const float f0  = __expf(m0 - mn0);
        const float f1  = __expf(m1 - mn1);
        m0 = mn0;  m1 = mn1;

#pragma unroll
        for (int j = 0; j < 16; j++) {
            s[j][0] = __expf(s[j][0] - mn0);
            s[j][1] = __expf(s[j][1] - mn0);
            s[j][2] = __expf(s[j][2] - mn1);
            s[j][3] = __expf(s[j][3] - mn1);
        }

        // rescale O and row-sum accumulators
#pragma unroll
        for (int j = 0; j < 8; j++) {
            o[j][0] *= f0; o[j][1] *= f0;
            o[j][2] *= f1; o[j][3] *= f1;
        }
        ls[0] *= f0; ls[1] *= f0; ls[2] *= f1; ls[3] *= f1;

        // O += P @ V ; ls += P @ ones   (P from registers)
#pragma unroll
        for (int kv = 0; kv < 128; kv += 16) {
            const int j0 = kv >> 3;
            uint32_t a[4];
            a[0] = pack2(s[j0][0],     s[j0][1]);
            a[1] = pack2(s[j0][2],     s[j0][3]);
            a[2] = pack2(s[j0 + 1][0], s[j0 + 1][1]);
            a[3] = pack2(s[j0 + 1][2], s[j0 + 1][3]);
            mma_f16(ls, a, bones);
#pragma unroll
            for (int jd = 0; jd < 8; jd += 2) {
                uint32_t b0[2], b1[2];
                const int row = kv + ((lane & 7) | (lane & 8));
                const int ch  = jd + (lane >> 4);
                ldsm_x4_t(b0[0], b0[1], b1[0], b1[1],
                          vb + row * 128 + ((ch ^ (row & 7)) << 4));
                mma_f16(o[jd],     a, b0);
                mma_f16(o[jd + 1], a, b1);
            }
        }
    }

    const float inv0 = 1.0f / ls[0];
    const float inv1 = 1.0f / ls[2];
    const int row0 = q0 + wm + g;
#pragma unroll
    for (int jd = 0; jd < 8; jd++) {
        const int col = h * DKH + jd * 8 + 2 * t;
        Oh[row0 * (HDIM / 2) + (col >> 1)]       = pack2(o[jd][0] * inv0, o[jd][1] * inv0);
        Oh[(row0 + 8) * (HDIM / 2) + (col >> 1)] = pack2(o[jd][2] * inv1, o[jd][3] * inv1);
    }
}

// ---------------------------------------------------------------------------
extern "C" void kernel_launch(void* const* d_in, const int* in_sizes, int n_in,
                              void* d_out, int out_size) {
    const float* x  = (const float*)d_in[0];
    const float* Wq = (const float*)d_in[1];
    const float* bq = (const float*)d_in[2];
    const float* Wk = (const float*)d_in[3];
    const float* bk = (const float*)d_in[4];
    const float* Wv = (const float*)d_in[5];
    const float* bv = (const float*)d_in[6];
    const float* Wo = (const float*)d_in[7];
    const float* bo = (const float*)d_in[8];
    float* out = (float*)d_out;

    uint32_t *xh, *wqh, *wkh, *wvh, *woh, *qh, *kh, *vh, *ah;
    cudaGetSymbolAddress((void**)&xh,  g_xh);
    cudaGetSymbolAddress((void**)&wqh, g_wqh);
    cudaGetSymbolAddress((void**)&wkh, g_wkh);
    cudaGetSymbolAddress((void**)&wvh, g_wvh);
    cudaGetSymbolAddress((void**)&woh, g_woh);
    cudaGetSymbolAddress((void**)&qh,  g_qh);
    cudaGetSymbolAddress((void**)&kh,  g_kh);
    cudaGetSymbolAddress((void**)&vh,  g_vh);
    cudaGetSymbolAddress((void**)&ah,  g_ah);

    const int total4 = XW4 + 4 * WW4;
    cvt_all_kernel<<<(total4 + 255) / 256, 256>>>(
        (const float4*)x, (const float4*)Wq, (const float4*)Wk,
        (const float4*)Wv, (const float4*)Wo,
        (uint2*)xh, (uint2*)wqh, (uint2*)wkh, (uint2*)wvh, (uint2*)woh);

    const int gemm_smem  = 3 * 32768;           // 96 KB
    const int flash_smem = 16384 + 2 * 32768;   // 80 KB
    cudaFuncSetAttribute(qkv_gemm_kernel,
                         cudaFuncAttributeMaxDynamicSharedMemorySize, gemm_smem);
    cudaFuncSetAttribute(gemm_f16_f32_kernel,
                         cudaFuncAttributeMaxDynamicSharedMemorySize, gemm_smem);
    cudaFuncSetAttribute(flash_f16_kernel,
                         cudaFuncAttributeMaxDynamicSharedMemorySize, flash_smem);

    qkv_gemm_kernel<<<dim3(HDIM / 128, TSEQ / 128, 3), 256, gemm_smem>>>(
        (const __half*)xh,
        (const __half*)wqh, (const __half*)wkh, (const __half*)wvh,
        bq, bk, bv, qh, kh, vh);

    flash_f16_kernel<<<dim3(TSEQ / 128, NHEADS), 256, flash_smem>>>(
        (const __half*)qh, (const __half*)kh, (const __half*)vh, ah);

    gemm_f16_f32_kernel<<<dim3(HDIM / 128, TSEQ / 128), 256, gemm_smem>>>(
        (const __half*)ah, (const __half*)woh, bo, out, TSEQ, HDIM, HDIM);
}